// round 7
// baseline (speedup 1.0000x reference)
#include <cuda_runtime.h>
#include <math.h>

// Problem constants (fixed shapes)
#define Nn 8192
#define Ee 131072
#define Cc 64
#define NELn 10
#define NBn 8
#define Gg 32
#define Hh 16
#define RMAXf 5.0f
#define AVGf 16.0f
#define TBINS 8192
#define Jn 4      // nodes per block in node kernels

// Scratch (device globals; no dynamic allocation allowed)
__device__ __align__(16) float g_h0[Nn * Cc];
__device__ int   g_elem[Nn];
__device__ __align__(16) float g_A[Nn * 4 * Cc];
__device__ __align__(16) float g_A2[Nn * 4 * Cc];
__device__ __align__(16) float g_out0[Nn * Cc];
__device__ __align__(16) float g_out1[Nn * 3 * Cc];
__device__ float g_d1[Nn * 3];
// Radial-MLP lookup tables (lerp over r in [0,RMAX]); 128 outputs per bin
__device__ __align__(16) float g_tab1[(TBINS + 8) * 128];
__device__ __align__(16) float g_tab2[(TBINS + 8) * 128];
// Edge sort (counting sort by receiver node)
__device__ int    g_deg[Nn];
__device__ int    g_off[Nn + 1];
__device__ int    g_cur[Nn];
__device__ int    g_esnd[Ee];
__device__ float4 g_egeo[Ee];   // (s3*vx/r, s3*vy/r, s3*vz/r, r*TBINS/RMAX)

// ---------------------------------------------------------------------------
__global__ void k_init(float* __restrict__ out_tot) {
    int i = blockIdx.x * blockDim.x + threadIdx.x;
    if (i < Nn) g_deg[i] = 0;
    if (i < Gg * 3) out_tot[i] = 0.0f;
}

// ---------------------------------------------------------------------------
__global__ void k_h0(const float* __restrict__ na, const float* __restrict__ We) {
    int n = blockIdx.x;
    int c = threadIdx.x;
    float acc = 0.0f;
#pragma unroll
    for (int k = 0; k < NELn; k++)
        acc = fmaf(na[n * NELn + k], We[k * Cc + c], acc);
    g_h0[n * Cc + c] = acc;
    if (c == 0) {
        int best = 0;
        float bv = na[n * NELn];
#pragma unroll
        for (int k = 1; k < NELn; k++) {
            float v = na[n * NELn + k];
            if (v > bv) { bv = v; best = k; }
        }
        g_elem[n] = best;
    }
}

// ---------------------------------------------------------------------------
// Radial-MLP lookup-table build (w(r) is a smooth function of r only).
// ---------------------------------------------------------------------------
__global__ void k_table(const float* __restrict__ Wa1, const float* __restrict__ Wb1,
                        const float* __restrict__ Wa2, const float* __restrict__ Wb2) {
    int bin  = blockIdx.x;               // 0..TBINS
    int pass = blockIdx.y;
    const float* Wa = pass ? Wa2 : Wa1;
    const float* Wb = pass ? Wb2 : Wb1;
    float* tab      = pass ? g_tab2 : g_tab1;
    int c = threadIdx.x;                 // 0..127

    float r = fmaxf((float)bin * (RMAXf / (float)TBINS), 1e-6f);
    float x = r * (1.0f / RMAXf);
    float x2 = x * x;
    float x5 = x2 * x2 * x;
    float env = 1.0f - 21.0f * x5 + 35.0f * x5 * x - 15.0f * x5 * x2;
    if (x >= 1.0f) env = 0.0f;

    float pref = sqrtf(2.0f / RMAXf) * env / r;
    float wphase = (3.14159265358979323846f / RMAXf) * r;

    __shared__ float hid[Cc];
    if (c < Cc) {
        float h = 0.0f;
#pragma unroll
        for (int nb = 0; nb < NBn; nb++) {
            float rbn = pref * sinf((float)(nb + 1) * wphase);
            h = fmaf(rbn, Wa[nb * Cc + c], h);
        }
        hid[c] = h / (1.0f + expf(-h));
    }
    __syncthreads();

    float acc = 0.0f;
#pragma unroll
    for (int k = 0; k < Cc; k++)
        acc = fmaf(hid[k], Wb[k * 256 + c], acc);
    tab[bin * 128 + c] = acc;
}

// ---------------------------------------------------------------------------
// Edge degree histogram (valid edges only: r < RMAX).
// ---------------------------------------------------------------------------
__global__ void k_hist(const float* __restrict__ pos,
                       const float* __restrict__ shifts,
                       const int* __restrict__ ei) {
    int e = blockIdx.x * blockDim.x + threadIdx.x;
    if (e >= Ee) return;
    int snd = ei[e];
    int rcv = ei[Ee + e];
    float vx = pos[rcv * 3 + 0] - pos[snd * 3 + 0] + shifts[e * 3 + 0];
    float vy = pos[rcv * 3 + 1] - pos[snd * 3 + 1] + shifts[e * 3 + 1];
    float vz = pos[rcv * 3 + 2] - pos[snd * 3 + 2] + shifts[e * 3 + 2];
    float r  = sqrtf(vx * vx + vy * vy + vz * vz + 1e-12f);
    if (r < RMAXf) atomicAdd(&g_deg[rcv], 1);
}

// ---------------------------------------------------------------------------
// Exclusive prefix sum over 8192 degrees. One block, 1024 threads x 8 each.
// ---------------------------------------------------------------------------
__global__ void k_scan() {
    __shared__ int sps[1024];
    int t = threadIdx.x;
    int v[8];
    int sum = 0;
#pragma unroll
    for (int j = 0; j < 8; j++) { v[j] = g_deg[t * 8 + j]; sum += v[j]; }
    sps[t] = sum;
    __syncthreads();
    for (int o = 1; o < 1024; o <<= 1) {
        int y = (t >= o) ? sps[t - o] : 0;
        __syncthreads();
        sps[t] += y;
        __syncthreads();
    }
    int excl = sps[t] - sum;
#pragma unroll
    for (int j = 0; j < 8; j++) {
        g_off[t * 8 + j] = excl;
        g_cur[t * 8 + j] = excl;
        excl += v[j];
    }
    if (t == 1023) g_off[Nn] = sps[1023];
}

// ---------------------------------------------------------------------------
// Scatter edge payload (geometry computed ONCE, reused by both passes).
// ---------------------------------------------------------------------------
__global__ void k_scatter(const float* __restrict__ pos,
                          const float* __restrict__ shifts,
                          const int* __restrict__ ei) {
    int e = blockIdx.x * blockDim.x + threadIdx.x;
    if (e >= Ee) return;
    int snd = ei[e];
    int rcv = ei[Ee + e];
    float vx = pos[rcv * 3 + 0] - pos[snd * 3 + 0] + shifts[e * 3 + 0];
    float vy = pos[rcv * 3 + 1] - pos[snd * 3 + 1] + shifts[e * 3 + 1];
    float vz = pos[rcv * 3 + 2] - pos[snd * 3 + 2] + shifts[e * 3 + 2];
    float r  = sqrtf(vx * vx + vy * vy + vz * vz + 1e-12f);
    if (r >= RMAXf) return;
    int p = atomicAdd(&g_cur[rcv], 1);
    const float s3 = 1.7320508075688772f;
    float inv = s3 / r;
    g_esnd[p] = snd;
    g_egeo[p] = make_float4(vx * inv, vy * inv, vz * inv,
                            r * ((float)TBINS / RMAXf));
}

// ---------------------------------------------------------------------------
// Gather aggregation: block per node, thread per channel. No float atomics.
// ---------------------------------------------------------------------------
__global__ void __launch_bounds__(64) k_agg(int pass) {
    const float* feat = pass ? g_out0 : g_h0;
    const float* tab  = pass ? g_tab2 : g_tab1;
    float* Aout       = pass ? g_A2   : g_A;

    int n = blockIdx.x;
    int d = threadIdx.x;
    int s = g_off[n];
    int e = g_off[n + 1];

    __shared__ int    ssnd[32];
    __shared__ float4 sgeo[32];

    float a0 = 0.0f, a1 = 0.0f, a2 = 0.0f, a3 = 0.0f;

    for (int base = s; base < e; base += 32) {
        int cnt = min(32, e - base);
        if (d < cnt) {
            ssnd[d] = g_esnd[base + d];
            sgeo[d] = g_egeo[base + d];
        }
        __syncthreads();
        for (int j = 0; j < cnt; j++) {
            float4 gv = sgeo[j];
            float t = gv.w;
            int   i = (int)t;
            float f = t - (float)i;
            const float* row = tab + i * 128;
            float r0 = row[d];
            float r1 = row[64 + d];
            float w0 = r0 + (row[128 + d] - r0) * f;
            float w1 = r1 + (row[192 + d] - r1) * f;
            float fs = feat[ssnd[j] * Cc + d];
            a0 = fmaf(fs, w0, a0);
            float g = fs * w1;
            a1 = fmaf(g, gv.x, a1);
            a2 = fmaf(g, gv.y, a2);
            a3 = fmaf(g, gv.z, a3);
        }
        __syncthreads();
    }

    float* A = Aout + n * 256;
    A[d]       = a0;
    A[64 + d]  = a1;
    A[128 + d] = a2;
    A[192 + d] = a3;
}

// ---------------------------------------------------------------------------
// Node layer 1: J=4 nodes per 64-thread block; shared-weight LDGs amortized
// across nodes via per-thread accumulators (phase-local, <=16 live).
// ---------------------------------------------------------------------------
__global__ void k_node1(const float* __restrict__ Wmix1,
                        const float* __restrict__ Wsc1,
                        const float* __restrict__ Wps,
                        const float* __restrict__ Wpv,
                        const float* __restrict__ Wp10,
                        const float* __restrict__ Wp11,
                        const float* __restrict__ wread1)
{
    int nb = blockIdx.x * Jn;
    int d = threadIdx.x;
    __shared__ float Ar[Jn][4][Cc];
    __shared__ float h0s[Jn][Cc];
    __shared__ float m0s[Jn][Cc];
    __shared__ float tm[Jn][3][Cc];
    __shared__ float red[Jn][3][2];
    __shared__ int   els[Jn];

    const float ia = 1.0f / AVGf;
#pragma unroll
    for (int j = 0; j < Jn; j++) {
#pragma unroll
        for (int k = 0; k < 4; k++)
            Ar[j][k][d] = g_A[(nb + j) * 256 + k * Cc + d] * ia;
        h0s[j][d] = g_h0[(nb + j) * Cc + d];
    }
    if (d < Jn) els[d] = g_elem[nb + d];
    __syncthreads();

    // h1: 16 accumulators, weights shared across the 4 nodes
    float a0[Jn], a1[Jn], a2[Jn], a3[Jn];
#pragma unroll
    for (int j = 0; j < Jn; j++) { a0[j] = a1[j] = a2[j] = a3[j] = 0.0f; }
#pragma unroll 4
    for (int c = 0; c < Cc; c++) {
        float w0 = Wmix1[c * Cc + d];              // L_OF: k=0 -> Wmix[0]
        float w1 = Wmix1[Cc * Cc + c * Cc + d];    //       k=1..3 -> Wmix[1]
#pragma unroll
        for (int j = 0; j < Jn; j++) {
            a0[j] = fmaf(Ar[j][0][c], w0, a0[j]);
            a1[j] = fmaf(Ar[j][1][c], w1, a1[j]);
            a2[j] = fmaf(Ar[j][2][c], w1, a2[j]);
            a3[j] = fmaf(Ar[j][3][c], w1, a3[j]);
        }
    }

    // polynomial gates
#pragma unroll
    for (int j = 0; j < Jn; j++) {
        int el = els[j];
        float s = a0[j];
        float ws0 = Wps[el * Cc + d];
        float ws1 = Wps[NELn * Cc + el * Cc + d];
        float ws2 = Wps[2 * NELn * Cc + el * Cc + d];
        float wv0 = Wpv[el * Cc + d];
        float wv1 = Wpv[NELn * Cc + el * Cc + d];
        float wv2 = Wpv[2 * NELn * Cc + el * Cc + d];
        m0s[j][d]   = s * (ws0 + s * (ws1 + s * ws2));
        float gv    = wv0 + s * (wv1 + s * wv2);
        tm[j][0][d] = a1[j] * gv;
        tm[j][1][d] = a2[j] * gv;
        tm[j][2][d] = a3[j] * gv;
    }
    __syncthreads();

    // out0 = m0 @ Wp1_0 (amortized) + h0 @ Wsc1[el] (per node)
    float o0[Jn];
#pragma unroll
    for (int j = 0; j < Jn; j++) o0[j] = 0.0f;
#pragma unroll 4
    for (int c = 0; c < Cc; c++) {
        float wp = Wp10[c * Cc + d];
#pragma unroll
        for (int j = 0; j < Jn; j++)
            o0[j] = fmaf(m0s[j][c], wp, o0[j]);
    }
#pragma unroll
    for (int j = 0; j < Jn; j++) {
        const float* Ws = Wsc1 + els[j] * Cc * Cc;
        float acc = o0[j];
#pragma unroll 8
        for (int c = 0; c < Cc; c++)
            acc = fmaf(h0s[j][c], Ws[c * Cc + d], acc);
        g_out0[(nb + j) * Cc + d] = acc;
    }

    // out1 = tm @ Wp1_1 (amortized); d1 = out1 . w_read1
    float o1[Jn][3];
#pragma unroll
    for (int j = 0; j < Jn; j++) { o1[j][0] = o1[j][1] = o1[j][2] = 0.0f; }
#pragma unroll 2
    for (int c = 0; c < Cc; c++) {
        float wp = Wp11[c * Cc + d];
#pragma unroll
        for (int j = 0; j < Jn; j++) {
            o1[j][0] = fmaf(tm[j][0][c], wp, o1[j][0]);
            o1[j][1] = fmaf(tm[j][1][c], wp, o1[j][1]);
            o1[j][2] = fmaf(tm[j][2][c], wp, o1[j][2]);
        }
    }
    float wr = wread1[d];
#pragma unroll
    for (int j = 0; j < Jn; j++) {
#pragma unroll
        for (int m = 0; m < 3; m++) {
            g_out1[((nb + j) * 3 + m) * Cc + d] = o1[j][m];
            float v = o1[j][m] * wr;
            v += __shfl_down_sync(0xffffffffu, v, 16);
            v += __shfl_down_sync(0xffffffffu, v, 8);
            v += __shfl_down_sync(0xffffffffu, v, 4);
            v += __shfl_down_sync(0xffffffffu, v, 2);
            v += __shfl_down_sync(0xffffffffu, v, 1);
            if ((d & 31) == 0) red[j][m][d >> 5] = v;
        }
    }
    __syncthreads();
    if (d < Jn * 3) {
        int j = d / 3, m = d % 3;
        g_d1[(nb + j) * 3 + m] = red[j][m][0] + red[j][m][1];
    }
}

// ---------------------------------------------------------------------------
// Node layer 2: J=4 nodes per 64-thread block.
// ---------------------------------------------------------------------------
__global__ void k_node2(const float* __restrict__ Wmix2,
                        const float* __restrict__ Wsc2,
                        const float* __restrict__ Wprod2,
                        const float* __restrict__ Wp2,
                        const float* __restrict__ Wv,
                        const float* __restrict__ Wg1,
                        const float* __restrict__ bg1,
                        const float* __restrict__ Wg2,
                        const float* __restrict__ bg2,
                        const float* __restrict__ wread2,
                        const int* __restrict__ batch,
                        const float* __restrict__ charges,
                        const float* __restrict__ pos,
                        float* __restrict__ out)
{
    int nb = blockIdx.x * Jn;
    int d = threadIdx.x;
    __shared__ float Ar[Jn][4][Cc];
    __shared__ float o1s[Jn][3][Cc];
    __shared__ float tm[Jn][3][Cc];
    __shared__ float o2s[Jn][3][Cc];
    __shared__ float vhs[Jn][3][Hh];
    __shared__ float invs[Jn][Hh];
    __shared__ float g1s[Jn][Hh];
    __shared__ float af[Jn][Hh];
    __shared__ int   els[Jn];

    const float ia = 1.0f / AVGf;
#pragma unroll
    for (int j = 0; j < Jn; j++) {
#pragma unroll
        for (int k = 0; k < 4; k++)
            Ar[j][k][d] = g_A2[(nb + j) * 256 + k * Cc + d] * ia;
#pragma unroll
        for (int m = 0; m < 3; m++)
            o1s[j][m][d] = g_out1[((nb + j) * 3 + m) * Cc + d];
    }
    if (d < Jn) els[d] = g_elem[nb + d];
    __syncthreads();

    // h2
    float a0[Jn], a1[Jn], a2[Jn], a3[Jn];
#pragma unroll
    for (int j = 0; j < Jn; j++) { a0[j] = a1[j] = a2[j] = a3[j] = 0.0f; }
#pragma unroll 4
    for (int c = 0; c < Cc; c++) {
        float w0 = Wmix2[c * Cc + d];
        float w1 = Wmix2[Cc * Cc + c * Cc + d];
#pragma unroll
        for (int j = 0; j < Jn; j++) {
            a0[j] = fmaf(Ar[j][0][c], w0, a0[j]);
            a1[j] = fmaf(Ar[j][1][c], w1, a1[j]);
            a2[j] = fmaf(Ar[j][2][c], w1, a2[j]);
            a3[j] = fmaf(Ar[j][3][c], w1, a3[j]);
        }
    }

#pragma unroll
    for (int j = 0; j < Jn; j++) {
        int el = els[j];
        float s2 = a0[j];
        float wv0 = Wprod2[el * Cc + d];
        float wv1 = Wprod2[NELn * Cc + el * Cc + d];
        float wv2 = Wprod2[2 * NELn * Cc + el * Cc + d];
        float gv2 = wv0 + s2 * (wv1 + s2 * wv2);
        tm[j][0][d] = a1[j] * gv2;
        tm[j][1][d] = a2[j] * gv2;
        tm[j][2][d] = a3[j] * gv2;
    }
    __syncthreads();

    // out2 = tm @ Wp2 (amortized) + o1 @ Wsc2[el] (amortized over m)
    float o2[Jn][3];
#pragma unroll
    for (int j = 0; j < Jn; j++) { o2[j][0] = o2[j][1] = o2[j][2] = 0.0f; }
#pragma unroll 2
    for (int c = 0; c < Cc; c++) {
        float wp = Wp2[c * Cc + d];
#pragma unroll
        for (int j = 0; j < Jn; j++) {
            o2[j][0] = fmaf(tm[j][0][c], wp, o2[j][0]);
            o2[j][1] = fmaf(tm[j][1][c], wp, o2[j][1]);
            o2[j][2] = fmaf(tm[j][2][c], wp, o2[j][2]);
        }
    }
#pragma unroll
    for (int j = 0; j < Jn; j++) {
        const float* Ws = Wsc2 + els[j] * Cc * Cc;
        float s0 = o2[j][0], s1 = o2[j][1], s2 = o2[j][2];
#pragma unroll 4
        for (int c = 0; c < Cc; c++) {
            float w = Ws[c * Cc + d];
            s0 = fmaf(o1s[j][0][c], w, s0);
            s1 = fmaf(o1s[j][1][c], w, s1);
            s2 = fmaf(o1s[j][2][c], w, s2);
        }
        o2s[j][0][d] = s0;
        o2s[j][1][d] = s1;
        o2s[j][2][d] = s2;
    }
    __syncthreads();

    // vh[j][m][h] = out2[j][m] @ Wv   (Jn*3*16 = 192 outputs)
#pragma unroll
    for (int t = d; t < Jn * 3 * Hh; t += Cc) {
        int j = t / (3 * Hh);
        int r = t - j * 3 * Hh;
        int m = r >> 4, h = r & 15;
        float acc = 0.0f;
#pragma unroll 8
        for (int c = 0; c < Cc; c++)
            acc = fmaf(o2s[j][m][c], Wv[c * Hh + h], acc);
        vhs[j][m][h] = acc;
    }
    __syncthreads();

    if (d < Jn * Hh) {
        int j = d >> 4, h = d & 15;
        float v0 = vhs[j][0][h], v1 = vhs[j][1][h], v2 = vhs[j][2][h];
        invs[j][h] = sqrtf(v0 * v0 + v1 * v1 + v2 * v2 + 1e-12f);
    }
    __syncthreads();

    if (d < Jn * Hh) {
        int j = d >> 4, h = d & 15;
        float pre = bg1[h];
#pragma unroll
        for (int hh = 0; hh < Hh; hh++)
            pre = fmaf(invs[j][hh], Wg1[hh * Hh + h], pre);
        g1s[j][h] = pre / (1.0f + expf(-pre));
    }
    __syncthreads();

    if (d < Jn * Hh) {
        int j = d >> 4, h = d & 15;
        float a = bg2[h];
#pragma unroll
        for (int hh = 0; hh < Hh; hh++)
            a = fmaf(g1s[j][hh], Wg2[hh * Hh + h], a);
        af[j][h] = a * wread2[h];
    }
    __syncthreads();

    if (d < Jn * 3) {
        int j = d / 3, m = d % 3;
        int n = nb + j;
        float d2 = 0.0f;
#pragma unroll
        for (int h = 0; h < Hh; h++)
            d2 = fmaf(vhs[j][m][h], af[j][h], d2);
        float dip = g_d1[n * 3 + m] + d2;
        out[Gg * 3 + n * 3 + m] = dip;
        int g = batch[n];
        atomicAdd(&out[g * 3 + m], dip + charges[n] * pos[n * 3 + m]);
    }
}

// ---------------------------------------------------------------------------
// Host launcher
// ---------------------------------------------------------------------------
extern "C" void kernel_launch(void* const* d_in, const int* in_sizes, int n_in,
                              void* d_out, int out_size) {
    int iei = -1;
    for (int i = 0; i < n_in; i++) {
        if (in_sizes[i] == 2 * Ee) { iei = i; break; }
    }
    if (iei < 0) iei = 4;

    const float* na      = (const float*)d_in[0];
    const float* pos     = (const float*)d_in[1];
    const float* shifts  = (const float*)d_in[2];
    const float* charges = (const float*)d_in[3];
    const int*   ei      = (const int*)d_in[iei];
    const int*   batch   = (const int*)d_in[iei + 1];

    int w;
    if (iei == 4) {
        w = (n_in > 6 && in_sizes[6] == 1) ? 7 : 6;
    } else {
        w = 4;
    }

    const float* W_embed = (const float*)d_in[w + 0];
    const float* Wr1a    = (const float*)d_in[w + 1];
    const float* Wr1b    = (const float*)d_in[w + 2];
    const float* Wmix1   = (const float*)d_in[w + 3];
    const float* Wsc1    = (const float*)d_in[w + 4];
    const float* Wp1s    = (const float*)d_in[w + 5];
    const float* Wp1v    = (const float*)d_in[w + 6];
    const float* Wp10    = (const float*)d_in[w + 7];
    const float* Wp11    = (const float*)d_in[w + 8];
    const float* wread1  = (const float*)d_in[w + 9];
    const float* Wr2a    = (const float*)d_in[w + 10];
    const float* Wr2b    = (const float*)d_in[w + 11];
    const float* Wmix2   = (const float*)d_in[w + 12];
    const float* Wsc2    = (const float*)d_in[w + 13];
    const float* Wprod2  = (const float*)d_in[w + 14];
    const float* Wp2     = (const float*)d_in[w + 15];
    const float* Wv      = (const float*)d_in[w + 16];
    const float* Wg1     = (const float*)d_in[w + 17];
    const float* bg1     = (const float*)d_in[w + 18];
    const float* Wg2     = (const float*)d_in[w + 19];
    const float* bg2     = (const float*)d_in[w + 20];
    const float* wread2  = (const float*)d_in[w + 21];

    float* out = (float*)d_out;

    k_init<<<32, 256>>>(out);
    k_h0<<<Nn, Cc>>>(na, W_embed);
    dim3 tg(TBINS + 1, 2);
    k_table<<<tg, 128>>>(Wr1a, Wr1b, Wr2a, Wr2b);
    k_hist<<<Ee / 256, 256>>>(pos, shifts, ei);
    k_scan<<<1, 1024>>>();
    k_scatter<<<Ee / 256, 256>>>(pos, shifts, ei);
    k_agg<<<Nn, Cc>>>(0);
    k_node1<<<Nn / Jn, Cc>>>(Wmix1, Wsc1, Wp1s, Wp1v, Wp10, Wp11, wread1);
    k_agg<<<Nn, Cc>>>(1);
    k_node2<<<Nn / Jn, Cc>>>(Wmix2, Wsc2, Wprod2, Wp2, Wv, Wg1, bg1, Wg2, bg2,
                             wread2, batch, charges, pos, out);
}

// round 8
// speedup vs baseline: 1.0896x; 1.0896x over previous
#include <cuda_runtime.h>
#include <math.h>

// Problem constants (fixed shapes)
#define Nn 8192
#define Ee 131072
#define Cc 64
#define NELn 10
#define NBn 8
#define Gg 32
#define Hh 16
#define RMAXf 5.0f
#define AVGf 16.0f
#define TBINS 8192

// Scratch (device globals; no dynamic allocation allowed)
__device__ __align__(16) float g_h0[Nn * Cc];
__device__ int   g_elem[Nn];
__device__ __align__(16) float g_out0[Nn * Cc];
__device__ __align__(16) float g_out1[Nn * 3 * Cc];
__device__ float g_d1[Nn * 3];
// Radial-MLP lookup tables (lerp over r in [0,RMAX]); 128 outputs per bin
__device__ __align__(16) float g_tab1[(TBINS + 8) * 128];
__device__ __align__(16) float g_tab2[(TBINS + 8) * 128];
// Edge sort (counting sort by receiver node)
__device__ int    g_deg[Nn];
__device__ int    g_off[Nn + 1];
__device__ int    g_cur[Nn];
__device__ int    g_esnd[Ee];
__device__ float4 g_egeo[Ee];   // (s3*vx/r, s3*vy/r, s3*vz/r, r*TBINS/RMAX)

// ---------------------------------------------------------------------------
__global__ void k_init(float* __restrict__ out_tot) {
    int i = blockIdx.x * blockDim.x + threadIdx.x;
    if (i < Nn) g_deg[i] = 0;
    if (i < Gg * 3) out_tot[i] = 0.0f;
}

// ---------------------------------------------------------------------------
__global__ void k_h0(const float* __restrict__ na, const float* __restrict__ We) {
    int n = blockIdx.x;
    int c = threadIdx.x;
    float acc = 0.0f;
#pragma unroll
    for (int k = 0; k < NELn; k++)
        acc = fmaf(na[n * NELn + k], We[k * Cc + c], acc);
    g_h0[n * Cc + c] = acc;
    if (c == 0) {
        int best = 0;
        float bv = na[n * NELn];
#pragma unroll
        for (int k = 1; k < NELn; k++) {
            float v = na[n * NELn + k];
            if (v > bv) { bv = v; best = k; }
        }
        g_elem[n] = best;
    }
}

// ---------------------------------------------------------------------------
// Radial-MLP lookup-table build (w(r) is a smooth function of r only).
// ---------------------------------------------------------------------------
__global__ void k_table(const float* __restrict__ Wa1, const float* __restrict__ Wb1,
                        const float* __restrict__ Wa2, const float* __restrict__ Wb2) {
    int bin  = blockIdx.x;               // 0..TBINS
    int pass = blockIdx.y;
    const float* Wa = pass ? Wa2 : Wa1;
    const float* Wb = pass ? Wb2 : Wb1;
    float* tab      = pass ? g_tab2 : g_tab1;
    int c = threadIdx.x;                 // 0..127

    float r = fmaxf((float)bin * (RMAXf / (float)TBINS), 1e-6f);
    float x = r * (1.0f / RMAXf);
    float x2 = x * x;
    float x5 = x2 * x2 * x;
    float env = 1.0f - 21.0f * x5 + 35.0f * x5 * x - 15.0f * x5 * x2;
    if (x >= 1.0f) env = 0.0f;

    float pref = sqrtf(2.0f / RMAXf) * env / r;
    float wphase = (3.14159265358979323846f / RMAXf) * r;

    __shared__ float hid[Cc];
    if (c < Cc) {
        float h = 0.0f;
#pragma unroll
        for (int nb = 0; nb < NBn; nb++) {
            float rbn = pref * sinf((float)(nb + 1) * wphase);
            h = fmaf(rbn, Wa[nb * Cc + c], h);
        }
        hid[c] = h / (1.0f + expf(-h));
    }
    __syncthreads();

    float acc = 0.0f;
#pragma unroll
    for (int k = 0; k < Cc; k++)
        acc = fmaf(hid[k], Wb[k * 256 + c], acc);
    tab[bin * 128 + c] = acc;
}

// ---------------------------------------------------------------------------
// Edge degree histogram (valid edges only: r < RMAX).
// ---------------------------------------------------------------------------
__global__ void k_hist(const float* __restrict__ pos,
                       const float* __restrict__ shifts,
                       const int* __restrict__ ei) {
    int e = blockIdx.x * blockDim.x + threadIdx.x;
    if (e >= Ee) return;
    int snd = ei[e];
    int rcv = ei[Ee + e];
    float vx = pos[rcv * 3 + 0] - pos[snd * 3 + 0] + shifts[e * 3 + 0];
    float vy = pos[rcv * 3 + 1] - pos[snd * 3 + 1] + shifts[e * 3 + 1];
    float vz = pos[rcv * 3 + 2] - pos[snd * 3 + 2] + shifts[e * 3 + 2];
    float r  = sqrtf(vx * vx + vy * vy + vz * vz + 1e-12f);
    if (r < RMAXf) atomicAdd(&g_deg[rcv], 1);
}

// ---------------------------------------------------------------------------
// Exclusive prefix sum over 8192 degrees. One block, 1024 threads x 8 each.
// ---------------------------------------------------------------------------
__global__ void k_scan() {
    __shared__ int sps[1024];
    int t = threadIdx.x;
    int v[8];
    int sum = 0;
#pragma unroll
    for (int j = 0; j < 8; j++) { v[j] = g_deg[t * 8 + j]; sum += v[j]; }
    sps[t] = sum;
    __syncthreads();
    for (int o = 1; o < 1024; o <<= 1) {
        int y = (t >= o) ? sps[t - o] : 0;
        __syncthreads();
        sps[t] += y;
        __syncthreads();
    }
    int excl = sps[t] - sum;
#pragma unroll
    for (int j = 0; j < 8; j++) {
        g_off[t * 8 + j] = excl;
        g_cur[t * 8 + j] = excl;
        excl += v[j];
    }
    if (t == 1023) g_off[Nn] = sps[1023];
}

// ---------------------------------------------------------------------------
// Scatter edge payload (geometry computed ONCE, reused by both passes).
// ---------------------------------------------------------------------------
__global__ void k_scatter(const float* __restrict__ pos,
                          const float* __restrict__ shifts,
                          const int* __restrict__ ei) {
    int e = blockIdx.x * blockDim.x + threadIdx.x;
    if (e >= Ee) return;
    int snd = ei[e];
    int rcv = ei[Ee + e];
    float vx = pos[rcv * 3 + 0] - pos[snd * 3 + 0] + shifts[e * 3 + 0];
    float vy = pos[rcv * 3 + 1] - pos[snd * 3 + 1] + shifts[e * 3 + 1];
    float vz = pos[rcv * 3 + 2] - pos[snd * 3 + 2] + shifts[e * 3 + 2];
    float r  = sqrtf(vx * vx + vy * vy + vz * vz + 1e-12f);
    if (r >= RMAXf) return;
    int p = atomicAdd(&g_cur[rcv], 1);
    const float s3 = 1.7320508075688772f;
    float inv = s3 / r;
    g_esnd[p] = snd;
    g_egeo[p] = make_float4(vx * inv, vy * inv, vz * inv,
                            r * ((float)TBINS / RMAXf));
}

// ---------------------------------------------------------------------------
// Shared aggregation routine: gather this node's edge segment, accumulate
// A[k][d] for k=0..3 in registers, write (scaled by 1/AVG) into smem Ar.
// Call with all 64 threads; Ar must be __shared__ float[4][Cc].
// ---------------------------------------------------------------------------
__device__ __forceinline__ void node_aggregate(
        int n, int d, const float* __restrict__ feat,
        const float* __restrict__ tab,
        float (*Ar)[Cc], int* ssnd, float4* sgeo)
{
    int s = g_off[n];
    int e = g_off[n + 1];
    float a0 = 0.0f, a1 = 0.0f, a2 = 0.0f, a3 = 0.0f;

    for (int base = s; base < e; base += 32) {
        int cnt = min(32, e - base);
        if (d < cnt) {
            ssnd[d] = g_esnd[base + d];
            sgeo[d] = g_egeo[base + d];
        }
        __syncthreads();
        for (int j = 0; j < cnt; j++) {
            float4 gv = sgeo[j];
            float t = gv.w;
            int   i = (int)t;
            float f = t - (float)i;
            const float* row = tab + i * 128;
            float r0 = row[d];
            float r1 = row[64 + d];
            float w0 = r0 + (row[128 + d] - r0) * f;
            float w1 = r1 + (row[192 + d] - r1) * f;
            float fs = feat[ssnd[j] * Cc + d];
            a0 = fmaf(fs, w0, a0);
            float g = fs * w1;
            a1 = fmaf(g, gv.x, a1);
            a2 = fmaf(g, gv.y, a2);
            a3 = fmaf(g, gv.z, a3);
        }
        __syncthreads();
    }

    const float ia = 1.0f / AVGf;
    Ar[0][d] = a0 * ia;
    Ar[1][d] = a1 * ia;
    Ar[2][d] = a2 * ia;
    Ar[3][d] = a3 * ia;
}

// ---------------------------------------------------------------------------
// Node layer 1 (fused with aggregation pass 1). One node per 64-thread block.
// Weight loads shared across k (h1) and across m (out1).
// ---------------------------------------------------------------------------
__global__ void __launch_bounds__(64) k_node1(
        const float* __restrict__ Wmix1,
        const float* __restrict__ Wsc1,
        const float* __restrict__ Wps,
        const float* __restrict__ Wpv,
        const float* __restrict__ Wp10,
        const float* __restrict__ Wp11,
        const float* __restrict__ wread1)
{
    int n = blockIdx.x;
    int d = threadIdx.x;
    __shared__ float Ar[4][Cc];
    __shared__ float h0s[Cc];
    __shared__ float m0s[Cc];
    __shared__ float tm[3][Cc];
    __shared__ float red[3][2];
    __shared__ int    ssnd[32];
    __shared__ float4 sgeo[32];

    // ---- aggregation (pass 1: feat = h0) ----
    node_aggregate(n, d, g_h0, g_tab1, Ar, ssnd, sgeo);
    h0s[d] = g_h0[n * Cc + d];
    __syncthreads();

    // ---- h1: weights shared across k (L_OF = 0,1,1,1) ----
    float h10 = 0.0f, h11 = 0.0f, h12 = 0.0f, h13 = 0.0f;
#pragma unroll 4
    for (int c = 0; c < Cc; c++) {
        float w0 = Wmix1[c * Cc + d];
        float w1 = Wmix1[Cc * Cc + c * Cc + d];
        h10 = fmaf(Ar[0][c], w0, h10);
        h11 = fmaf(Ar[1][c], w1, h11);
        h12 = fmaf(Ar[2][c], w1, h12);
        h13 = fmaf(Ar[3][c], w1, h13);
    }

    // ---- polynomial gates ----
    int el = g_elem[n];
    float s = h10;
    float ws0 = Wps[el * Cc + d], ws1 = Wps[NELn * Cc + el * Cc + d], ws2 = Wps[2 * NELn * Cc + el * Cc + d];
    float wv0 = Wpv[el * Cc + d], wv1 = Wpv[NELn * Cc + el * Cc + d], wv2 = Wpv[2 * NELn * Cc + el * Cc + d];
    m0s[d]   = s * (ws0 + s * (ws1 + s * ws2));
    float gv = wv0 + s * (wv1 + s * wv2);
    tm[0][d] = h11 * gv;
    tm[1][d] = h12 * gv;
    tm[2][d] = h13 * gv;
    __syncthreads();

    // ---- out0 = m0 @ Wp1_0 + h0 @ Wsc1[el] (fused c-loop) ----
    float o0 = 0.0f;
    const float* Ws = Wsc1 + el * Cc * Cc;
#pragma unroll 4
    for (int c = 0; c < Cc; c++) {
        o0 = fmaf(h0s[c], Ws[c * Cc + d], o0);
        o0 = fmaf(m0s[c], Wp10[c * Cc + d], o0);
    }
    g_out0[n * Cc + d] = o0;

    // ---- out1 = tm @ Wp1_1, weight shared across m ----
    float o10 = 0.0f, o11 = 0.0f, o12 = 0.0f;
#pragma unroll 4
    for (int c = 0; c < Cc; c++) {
        float wp = Wp11[c * Cc + d];
        o10 = fmaf(tm[0][c], wp, o10);
        o11 = fmaf(tm[1][c], wp, o11);
        o12 = fmaf(tm[2][c], wp, o12);
    }

    float wr = wread1[d];
    float o1a[3] = {o10, o11, o12};
#pragma unroll
    for (int m = 0; m < 3; m++) {
        g_out1[(n * 3 + m) * Cc + d] = o1a[m];
        float v = o1a[m] * wr;
        v += __shfl_down_sync(0xffffffffu, v, 16);
        v += __shfl_down_sync(0xffffffffu, v, 8);
        v += __shfl_down_sync(0xffffffffu, v, 4);
        v += __shfl_down_sync(0xffffffffu, v, 2);
        v += __shfl_down_sync(0xffffffffu, v, 1);
        if ((d & 31) == 0) red[m][d >> 5] = v;
    }
    __syncthreads();
    if (d < 3) g_d1[n * 3 + d] = red[d][0] + red[d][1];
}

// ---------------------------------------------------------------------------
// Node layer 2 (fused with aggregation pass 2). One node per 64-thread block.
// Wsc2/Wp2 loads shared across m in a single fused c-loop.
// ---------------------------------------------------------------------------
__global__ void __launch_bounds__(64) k_node2(
        const float* __restrict__ Wmix2,
        const float* __restrict__ Wsc2,
        const float* __restrict__ Wprod2,
        const float* __restrict__ Wp2,
        const float* __restrict__ Wv,
        const float* __restrict__ Wg1,
        const float* __restrict__ bg1,
        const float* __restrict__ Wg2,
        const float* __restrict__ bg2,
        const float* __restrict__ wread2,
        const int* __restrict__ batch,
        const float* __restrict__ charges,
        const float* __restrict__ pos,
        float* __restrict__ out)
{
    int n = blockIdx.x;
    int d = threadIdx.x;
    __shared__ float Ar[4][Cc];
    __shared__ float o1s[3][Cc];
    __shared__ float tm[3][Cc];
    __shared__ float o2s[3][Cc];
    __shared__ float vhs[3][Hh];
    __shared__ float invs[Hh];
    __shared__ float g1s[Hh];
    __shared__ float af[Hh];
    __shared__ int    ssnd[32];
    __shared__ float4 sgeo[32];

    // ---- aggregation (pass 2: feat = out0) ----
    node_aggregate(n, d, g_out0, g_tab2, Ar, ssnd, sgeo);
#pragma unroll
    for (int m = 0; m < 3; m++) o1s[m][d] = g_out1[(n * 3 + m) * Cc + d];
    __syncthreads();

    // ---- h2: weights shared across k ----
    float h20 = 0.0f, h21 = 0.0f, h22 = 0.0f, h23 = 0.0f;
#pragma unroll 4
    for (int c = 0; c < Cc; c++) {
        float w0 = Wmix2[c * Cc + d];
        float w1 = Wmix2[Cc * Cc + c * Cc + d];
        h20 = fmaf(Ar[0][c], w0, h20);
        h21 = fmaf(Ar[1][c], w1, h21);
        h22 = fmaf(Ar[2][c], w1, h22);
        h23 = fmaf(Ar[3][c], w1, h23);
    }

    int el = g_elem[n];
    float s2 = h20;
    float wv0 = Wprod2[el * Cc + d], wv1 = Wprod2[NELn * Cc + el * Cc + d], wv2 = Wprod2[2 * NELn * Cc + el * Cc + d];
    float gv2 = wv0 + s2 * (wv1 + s2 * wv2);
    tm[0][d] = h21 * gv2;
    tm[1][d] = h22 * gv2;
    tm[2][d] = h23 * gv2;
    __syncthreads();

    // ---- out2 = tm @ Wp2 + o1 @ Wsc2[el]; both weights shared across m ----
    float s0 = 0.0f, s1 = 0.0f, s2a = 0.0f;
    const float* Ws = Wsc2 + el * Cc * Cc;
#pragma unroll 4
    for (int c = 0; c < Cc; c++) {
        float w  = Ws[c * Cc + d];
        float wp = Wp2[c * Cc + d];
        s0  = fmaf(o1s[0][c], w, s0);
        s1  = fmaf(o1s[1][c], w, s1);
        s2a = fmaf(o1s[2][c], w, s2a);
        s0  = fmaf(tm[0][c], wp, s0);
        s1  = fmaf(tm[1][c], wp, s1);
        s2a = fmaf(tm[2][c], wp, s2a);
    }
    o2s[0][d] = s0;
    o2s[1][d] = s1;
    o2s[2][d] = s2a;
    __syncthreads();

    // ---- vh[m][h] = out2[m] @ Wv (48 outputs) ----
    if (d < 48) {
        int m = d >> 4, h = d & 15;
        float acc = 0.0f;
#pragma unroll 8
        for (int c = 0; c < Cc; c++)
            acc = fmaf(o2s[m][c], Wv[c * Hh + h], acc);
        vhs[m][h] = acc;
    }
    __syncthreads();

    if (d < Hh) {
        float v0 = vhs[0][d], v1 = vhs[1][d], v2 = vhs[2][d];
        invs[d] = sqrtf(v0 * v0 + v1 * v1 + v2 * v2 + 1e-12f);
    }
    __syncthreads();

    if (d < Hh) {
        float pre = bg1[d];
#pragma unroll
        for (int h = 0; h < Hh; h++) pre = fmaf(invs[h], Wg1[h * Hh + d], pre);
        g1s[d] = pre / (1.0f + expf(-pre));
    }
    __syncthreads();

    if (d < Hh) {
        float a = bg2[d];
#pragma unroll
        for (int h = 0; h < Hh; h++) a = fmaf(g1s[h], Wg2[h * Hh + d], a);
        af[d] = a * wread2[d];
    }
    __syncthreads();

    if (d < 3) {
        float d2 = 0.0f;
#pragma unroll
        for (int h = 0; h < Hh; h++) d2 = fmaf(vhs[d][h], af[h], d2);
        float dip = g_d1[n * 3 + d] + d2;
        out[Gg * 3 + n * 3 + d] = dip;
        int g = batch[n];
        atomicAdd(&out[g * 3 + d], dip + charges[n] * pos[n * 3 + d]);
    }
}

// ---------------------------------------------------------------------------
// Host launcher
// ---------------------------------------------------------------------------
extern "C" void kernel_launch(void* const* d_in, const int* in_sizes, int n_in,
                              void* d_out, int out_size) {
    int iei = -1;
    for (int i = 0; i < n_in; i++) {
        if (in_sizes[i] == 2 * Ee) { iei = i; break; }
    }
    if (iei < 0) iei = 4;

    const float* na      = (const float*)d_in[0];
    const float* pos     = (const float*)d_in[1];
    const float* shifts  = (const float*)d_in[2];
    const float* charges = (const float*)d_in[3];
    const int*   ei      = (const int*)d_in[iei];
    const int*   batch   = (const int*)d_in[iei + 1];

    int w;
    if (iei == 4) {
        w = (n_in > 6 && in_sizes[6] == 1) ? 7 : 6;
    } else {
        w = 4;
    }

    const float* W_embed = (const float*)d_in[w + 0];
    const float* Wr1a    = (const float*)d_in[w + 1];
    const float* Wr1b    = (const float*)d_in[w + 2];
    const float* Wmix1   = (const float*)d_in[w + 3];
    const float* Wsc1    = (const float*)d_in[w + 4];
    const float* Wp1s    = (const float*)d_in[w + 5];
    const float* Wp1v    = (const float*)d_in[w + 6];
    const float* Wp10    = (const float*)d_in[w + 7];
    const float* Wp11    = (const float*)d_in[w + 8];
    const float* wread1  = (const float*)d_in[w + 9];
    const float* Wr2a    = (const float*)d_in[w + 10];
    const float* Wr2b    = (const float*)d_in[w + 11];
    const float* Wmix2   = (const float*)d_in[w + 12];
    const float* Wsc2    = (const float*)d_in[w + 13];
    const float* Wprod2  = (const float*)d_in[w + 14];
    const float* Wp2     = (const float*)d_in[w + 15];
    const float* Wv      = (const float*)d_in[w + 16];
    const float* Wg1     = (const float*)d_in[w + 17];
    const float* bg1     = (const float*)d_in[w + 18];
    const float* Wg2     = (const float*)d_in[w + 19];
    const float* bg2     = (const float*)d_in[w + 20];
    const float* wread2  = (const float*)d_in[w + 21];

    float* out = (float*)d_out;

    k_init<<<32, 256>>>(out);
    k_h0<<<Nn, Cc>>>(na, W_embed);
    dim3 tg(TBINS + 1, 2);
    k_table<<<tg, 128>>>(Wr1a, Wr1b, Wr2a, Wr2b);
    k_hist<<<Ee / 256, 256>>>(pos, shifts, ei);
    k_scan<<<1, 1024>>>();
    k_scatter<<<Ee / 256, 256>>>(pos, shifts, ei);
    k_node1<<<Nn, Cc>>>(Wmix1, Wsc1, Wp1s, Wp1v, Wp10, Wp11, wread1);
    k_node2<<<Nn, Cc>>>(Wmix2, Wsc2, Wprod2, Wp2, Wv, Wg1, bg1, Wg2, bg2,
                        wread2, batch, charges, pos, out);
}

// round 9
// speedup vs baseline: 1.4957x; 1.3727x over previous
#include <cuda_runtime.h>
#include <math.h>

// Problem constants (fixed shapes)
#define Nn 8192
#define Ee 131072
#define Cc 64
#define NELn 10
#define NBn 8
#define Gg 32
#define Hh 16
#define RMAXf 5.0f
#define AVGf 16.0f
#define TBINS 2048

// Scratch (device globals; no dynamic allocation allowed)
__device__ __align__(16) float g_h0[Nn * Cc];
__device__ int   g_elem[Nn];
__device__ __align__(16) float g_A[Nn * 4 * Cc];
__device__ __align__(16) float g_A2[Nn * 4 * Cc];
__device__ __align__(16) float g_out0[Nn * Cc];
__device__ __align__(16) float g_out1[Nn * 3 * Cc];
__device__ float g_d1[Nn * 3];
// Radial-MLP lookup tables (lerp over r in [0,RMAX]); 128 outputs per bin,
// pre-scaled by 1/AVG. Layout per bin: [w0(64) | w1(64)].
__device__ __align__(16) float g_tab1[(TBINS + 8) * 128];
__device__ __align__(16) float g_tab2[(TBINS + 8) * 128];
// Edge sort (counting sort by receiver node)
__device__ int    g_deg[Nn];
__device__ int    g_off[Nn + 1];
__device__ int    g_cur[Nn];
__device__ int    g_esnd[Ee];
__device__ float4 g_egeo[Ee];   // (s3*vx/r, s3*vy/r, s3*vz/r, r*TBINS/RMAX)

#define LD4(p) (*(const float4*)(p))
#define ST4(p, v) (*(float4*)(p) = (v))

__device__ __forceinline__ void fma4(float4& acc, float4 w, float s) {
    acc.x = fmaf(w.x, s, acc.x);
    acc.y = fmaf(w.y, s, acc.y);
    acc.z = fmaf(w.z, s, acc.z);
    acc.w = fmaf(w.w, s, acc.w);
}

// ---------------------------------------------------------------------------
// h0 = node_attrs @ W_embed ; elem argmax ; fused init of g_deg and totals.
// ---------------------------------------------------------------------------
__global__ void k_h0(const float* __restrict__ na, const float* __restrict__ We,
                     float* __restrict__ out_tot) {
    int n = blockIdx.x;
    int c = threadIdx.x;
    float acc = 0.0f;
#pragma unroll
    for (int k = 0; k < NELn; k++)
        acc = fmaf(na[n * NELn + k], We[k * Cc + c], acc);
    g_h0[n * Cc + c] = acc;
    if (c == 0) {
        int best = 0;
        float bv = na[n * NELn];
#pragma unroll
        for (int k = 1; k < NELn; k++) {
            float v = na[n * NELn + k];
            if (v > bv) { bv = v; best = k; }
        }
        g_elem[n] = best;
        g_deg[n] = 0;
    }
    if (c == 1 && n < Gg * 3) out_tot[n] = 0.0f;
}

// ---------------------------------------------------------------------------
// Radial-MLP lookup-table build (w(r) smooth in r); scaled by 1/AVG.
// ---------------------------------------------------------------------------
__global__ void k_table(const float* __restrict__ Wa1, const float* __restrict__ Wb1,
                        const float* __restrict__ Wa2, const float* __restrict__ Wb2) {
    int bin  = blockIdx.x;               // 0..TBINS
    int pass = blockIdx.y;
    const float* Wa = pass ? Wa2 : Wa1;
    const float* Wb = pass ? Wb2 : Wb1;
    float* tab      = pass ? g_tab2 : g_tab1;
    int c = threadIdx.x;                 // 0..127

    float r = fmaxf((float)bin * (RMAXf / (float)TBINS), 1e-6f);
    float x = r * (1.0f / RMAXf);
    float x2 = x * x;
    float x5 = x2 * x2 * x;
    float env = 1.0f - 21.0f * x5 + 35.0f * x5 * x - 15.0f * x5 * x2;
    if (x >= 1.0f) env = 0.0f;

    float pref = sqrtf(2.0f / RMAXf) * env / r;
    float wphase = (3.14159265358979323846f / RMAXf) * r;

    __shared__ float hid[Cc];
    if (c < Cc) {
        float h = 0.0f;
#pragma unroll
        for (int nb = 0; nb < NBn; nb++) {
            float rbn = pref * sinf((float)(nb + 1) * wphase);
            h = fmaf(rbn, Wa[nb * Cc + c], h);
        }
        hid[c] = h / (1.0f + expf(-h));
    }
    __syncthreads();

    float acc = 0.0f;
#pragma unroll
    for (int k = 0; k < Cc; k++)
        acc = fmaf(hid[k], Wb[k * 256 + c], acc);
    tab[bin * 128 + c] = acc * (1.0f / AVGf);
}

// ---------------------------------------------------------------------------
// Edge degree histogram (valid edges only: r < RMAX).
// ---------------------------------------------------------------------------
__global__ void k_hist(const float* __restrict__ pos,
                       const float* __restrict__ shifts,
                       const int* __restrict__ ei) {
    int e = blockIdx.x * blockDim.x + threadIdx.x;
    if (e >= Ee) return;
    int snd = ei[e];
    int rcv = ei[Ee + e];
    float vx = pos[rcv * 3 + 0] - pos[snd * 3 + 0] + shifts[e * 3 + 0];
    float vy = pos[rcv * 3 + 1] - pos[snd * 3 + 1] + shifts[e * 3 + 1];
    float vz = pos[rcv * 3 + 2] - pos[snd * 3 + 2] + shifts[e * 3 + 2];
    float r  = sqrtf(vx * vx + vy * vy + vz * vz + 1e-12f);
    if (r < RMAXf) atomicAdd(&g_deg[rcv], 1);
}

// ---------------------------------------------------------------------------
// Exclusive prefix sum over 8192 degrees. One block, 1024 threads x 8 each.
// ---------------------------------------------------------------------------
__global__ void k_scan() {
    __shared__ int sps[1024];
    int t = threadIdx.x;
    int v[8];
    int sum = 0;
#pragma unroll
    for (int j = 0; j < 8; j++) { v[j] = g_deg[t * 8 + j]; sum += v[j]; }
    sps[t] = sum;
    __syncthreads();
    for (int o = 1; o < 1024; o <<= 1) {
        int y = (t >= o) ? sps[t - o] : 0;
        __syncthreads();
        sps[t] += y;
        __syncthreads();
    }
    int excl = sps[t] - sum;
#pragma unroll
    for (int j = 0; j < 8; j++) {
        g_off[t * 8 + j] = excl;
        g_cur[t * 8 + j] = excl;
        excl += v[j];
    }
    if (t == 1023) g_off[Nn] = sps[1023];
}

// ---------------------------------------------------------------------------
// Scatter edge payload (geometry computed ONCE, reused by both passes).
// ---------------------------------------------------------------------------
__global__ void k_scatter(const float* __restrict__ pos,
                          const float* __restrict__ shifts,
                          const int* __restrict__ ei) {
    int e = blockIdx.x * blockDim.x + threadIdx.x;
    if (e >= Ee) return;
    int snd = ei[e];
    int rcv = ei[Ee + e];
    float vx = pos[rcv * 3 + 0] - pos[snd * 3 + 0] + shifts[e * 3 + 0];
    float vy = pos[rcv * 3 + 1] - pos[snd * 3 + 1] + shifts[e * 3 + 1];
    float vz = pos[rcv * 3 + 2] - pos[snd * 3 + 2] + shifts[e * 3 + 2];
    float r  = sqrtf(vx * vx + vy * vy + vz * vz + 1e-12f);
    if (r >= RMAXf) return;
    int p = atomicAdd(&g_cur[rcv], 1);
    const float s3 = 1.7320508075688772f;
    float inv = s3 / r;
    g_esnd[p] = snd;
    g_egeo[p] = make_float4(vx * inv, vy * inv, vz * inv,
                            r * ((float)TBINS / RMAXf));
}

// ---------------------------------------------------------------------------
// Gather aggregation: block per node, thread per channel. No float atomics.
// (A is pre-scaled by 1/AVG via the table.)
// ---------------------------------------------------------------------------
__global__ void __launch_bounds__(64) k_agg(int pass) {
    const float* feat = pass ? g_out0 : g_h0;
    const float* tab  = pass ? g_tab2 : g_tab1;
    float* Aout       = pass ? g_A2   : g_A;

    int n = blockIdx.x;
    int d = threadIdx.x;
    int s = g_off[n];
    int e = g_off[n + 1];

    __shared__ int    ssnd[32];
    __shared__ float4 sgeo[32];

    float a0 = 0.0f, a1 = 0.0f, a2 = 0.0f, a3 = 0.0f;

    for (int base = s; base < e; base += 32) {
        int cnt = min(32, e - base);
        if (d < cnt) {
            ssnd[d] = g_esnd[base + d];
            sgeo[d] = g_egeo[base + d];
        }
        __syncthreads();
        for (int j = 0; j < cnt; j++) {
            float4 gv = sgeo[j];
            float t = gv.w;
            int   i = (int)t;
            float f = t - (float)i;
            const float* row = tab + i * 128;
            float r0 = row[d];
            float r1 = row[64 + d];
            float w0 = r0 + (row[128 + d] - r0) * f;
            float w1 = r1 + (row[192 + d] - r1) * f;
            float fs = feat[ssnd[j] * Cc + d];
            a0 = fmaf(fs, w0, a0);
            float g = fs * w1;
            a1 = fmaf(g, gv.x, a1);
            a2 = fmaf(g, gv.y, a2);
            a3 = fmaf(g, gv.z, a3);
        }
        __syncthreads();
    }

    float* A = Aout + n * 256;
    A[d]       = a0;
    A[64 + d]  = a1;
    A[128 + d] = a2;
    A[192 + d] = a3;
}

// ---------------------------------------------------------------------------
// Node layer 1. 64 threads = 4 nodes x 16 lanes; each thread owns 4 channels
// (float4). All weight loads are LDG.128, shared by the 2 nodes in a warp.
// Named float4 accumulators only -> no spillable register arrays.
// ---------------------------------------------------------------------------
__global__ void __launch_bounds__(64) k_node1(
        const float* __restrict__ Wmix1,
        const float* __restrict__ Wsc1,
        const float* __restrict__ Wps,
        const float* __restrict__ Wpv,
        const float* __restrict__ Wp10,
        const float* __restrict__ Wp11,
        const float* __restrict__ wread1)
{
    int t = threadIdx.x;
    int j = t >> 4;          // node in block (0..3)
    int q = t & 15;          // channel quad (0..15)
    int d4 = q << 2;
    int n = blockIdx.x * 4 + j;

    __shared__ float As[4][4][Cc];
    __shared__ float h0s[4][Cc];
    __shared__ float m0s[4][Cc];
    __shared__ float tms[4][3][Cc];

#pragma unroll
    for (int k = 0; k < 4; k++)
        ST4(&As[j][k][d4], LD4(g_A + n * 256 + k * 64 + d4));
    ST4(&h0s[j][d4], LD4(g_h0 + n * 64 + d4));
    __syncwarp();

    // ---- h1[k][d] = sum_c A[k][c] * Wmix[LOF[k]][c][d]  (LOF = 0,1,1,1) ----
    float4 hv0 = {0,0,0,0}, hv1 = hv0, hv2 = hv0, hv3 = hv0;
#pragma unroll 4
    for (int c = 0; c < Cc; c++) {
        float4 w0 = LD4(Wmix1 + c * 64 + d4);
        float4 w1 = LD4(Wmix1 + 4096 + c * 64 + d4);
        fma4(hv0, w0, As[j][0][c]);
        fma4(hv1, w1, As[j][1][c]);
        fma4(hv2, w1, As[j][2][c]);
        fma4(hv3, w1, As[j][3][c]);
    }

    // ---- polynomial gates ----
    int el = g_elem[n];
    float4 ws0 = LD4(Wps + el * 64 + d4);
    float4 ws1 = LD4(Wps + NELn * 64 + el * 64 + d4);
    float4 ws2 = LD4(Wps + 2 * NELn * 64 + el * 64 + d4);
    float4 wv0 = LD4(Wpv + el * 64 + d4);
    float4 wv1 = LD4(Wpv + NELn * 64 + el * 64 + d4);
    float4 wv2 = LD4(Wpv + 2 * NELn * 64 + el * 64 + d4);

    float4 m0, gv;
    m0.x = hv0.x * (ws0.x + hv0.x * (ws1.x + hv0.x * ws2.x));
    m0.y = hv0.y * (ws0.y + hv0.y * (ws1.y + hv0.y * ws2.y));
    m0.z = hv0.z * (ws0.z + hv0.z * (ws1.z + hv0.z * ws2.z));
    m0.w = hv0.w * (ws0.w + hv0.w * (ws1.w + hv0.w * ws2.w));
    gv.x = wv0.x + hv0.x * (wv1.x + hv0.x * wv2.x);
    gv.y = wv0.y + hv0.y * (wv1.y + hv0.y * wv2.y);
    gv.z = wv0.z + hv0.z * (wv1.z + hv0.z * wv2.z);
    gv.w = wv0.w + hv0.w * (wv1.w + hv0.w * wv2.w);

    ST4(&m0s[j][d4], m0);
    float4 t0 = make_float4(hv1.x * gv.x, hv1.y * gv.y, hv1.z * gv.z, hv1.w * gv.w);
    float4 t1 = make_float4(hv2.x * gv.x, hv2.y * gv.y, hv2.z * gv.z, hv2.w * gv.w);
    float4 t2 = make_float4(hv3.x * gv.x, hv3.y * gv.y, hv3.z * gv.z, hv3.w * gv.w);
    ST4(&tms[j][0][d4], t0);
    ST4(&tms[j][1][d4], t1);
    ST4(&tms[j][2][d4], t2);
    __syncwarp();

    // ---- out0 = m0 @ Wp1_0 + h0 @ Wsc1[el] ----
    float4 o0 = {0,0,0,0};
    const float* Ws = Wsc1 + el * 4096;
#pragma unroll 4
    for (int c = 0; c < Cc; c++) {
        float4 wsc = LD4(Ws + c * 64 + d4);
        float4 wp  = LD4(Wp10 + c * 64 + d4);
        fma4(o0, wsc, h0s[j][c]);
        fma4(o0, wp,  m0s[j][c]);
    }
    ST4(g_out0 + n * 64 + d4, o0);

    // ---- out1 = tm @ Wp1_1 ; d1 = out1 . w_read1 ----
    float4 om0 = {0,0,0,0}, om1 = om0, om2 = om0;
#pragma unroll 4
    for (int c = 0; c < Cc; c++) {
        float4 wp = LD4(Wp11 + c * 64 + d4);
        fma4(om0, wp, tms[j][0][c]);
        fma4(om1, wp, tms[j][1][c]);
        fma4(om2, wp, tms[j][2][c]);
    }
    ST4(g_out1 + (n * 3 + 0) * 64 + d4, om0);
    ST4(g_out1 + (n * 3 + 1) * 64 + d4, om1);
    ST4(g_out1 + (n * 3 + 2) * 64 + d4, om2);

    float4 wrv = LD4(wread1 + d4);
#pragma unroll
    for (int m = 0; m < 3; m++) {
        float4 o = (m == 0) ? om0 : ((m == 1) ? om1 : om2);
        float v = o.x * wrv.x + o.y * wrv.y + o.z * wrv.z + o.w * wrv.w;
        v += __shfl_down_sync(0xffffffffu, v, 8);
        v += __shfl_down_sync(0xffffffffu, v, 4);
        v += __shfl_down_sync(0xffffffffu, v, 2);
        v += __shfl_down_sync(0xffffffffu, v, 1);
        if (q == 0) g_d1[n * 3 + m] = v;
    }
}

// ---------------------------------------------------------------------------
// Node layer 2. Same 4-nodes/4-channels layout; tail phases map q <-> h.
// ---------------------------------------------------------------------------
__global__ void __launch_bounds__(64) k_node2(
        const float* __restrict__ Wmix2,
        const float* __restrict__ Wsc2,
        const float* __restrict__ Wprod2,
        const float* __restrict__ Wp2,
        const float* __restrict__ Wv,
        const float* __restrict__ Wg1,
        const float* __restrict__ bg1,
        const float* __restrict__ Wg2,
        const float* __restrict__ bg2,
        const float* __restrict__ wread2,
        const int* __restrict__ batch,
        const float* __restrict__ charges,
        const float* __restrict__ pos,
        float* __restrict__ out)
{
    int t = threadIdx.x;
    int j = t >> 4;
    int q = t & 15;
    int d4 = q << 2;
    int n = blockIdx.x * 4 + j;

    __shared__ float As[4][4][Cc];
    __shared__ float o1s[4][3][Cc];
    __shared__ float tms[4][3][Cc];
    __shared__ float o2s[4][3][Cc];
    __shared__ float vhs[4][3][Hh];
    __shared__ float invs[4][Hh];
    __shared__ float g1s[4][Hh];
    __shared__ float af[4][Hh];

#pragma unroll
    for (int k = 0; k < 4; k++)
        ST4(&As[j][k][d4], LD4(g_A2 + n * 256 + k * 64 + d4));
#pragma unroll
    for (int m = 0; m < 3; m++)
        ST4(&o1s[j][m][d4], LD4(g_out1 + (n * 3 + m) * 64 + d4));
    __syncwarp();

    // ---- h2 ----
    float4 hv0 = {0,0,0,0}, hv1 = hv0, hv2 = hv0, hv3 = hv0;
#pragma unroll 4
    for (int c = 0; c < Cc; c++) {
        float4 w0 = LD4(Wmix2 + c * 64 + d4);
        float4 w1 = LD4(Wmix2 + 4096 + c * 64 + d4);
        fma4(hv0, w0, As[j][0][c]);
        fma4(hv1, w1, As[j][1][c]);
        fma4(hv2, w1, As[j][2][c]);
        fma4(hv3, w1, As[j][3][c]);
    }

    int el = g_elem[n];
    float4 wv0 = LD4(Wprod2 + el * 64 + d4);
    float4 wv1 = LD4(Wprod2 + NELn * 64 + el * 64 + d4);
    float4 wv2 = LD4(Wprod2 + 2 * NELn * 64 + el * 64 + d4);
    float4 gv;
    gv.x = wv0.x + hv0.x * (wv1.x + hv0.x * wv2.x);
    gv.y = wv0.y + hv0.y * (wv1.y + hv0.y * wv2.y);
    gv.z = wv0.z + hv0.z * (wv1.z + hv0.z * wv2.z);
    gv.w = wv0.w + hv0.w * (wv1.w + hv0.w * wv2.w);

    ST4(&tms[j][0][d4], make_float4(hv1.x*gv.x, hv1.y*gv.y, hv1.z*gv.z, hv1.w*gv.w));
    ST4(&tms[j][1][d4], make_float4(hv2.x*gv.x, hv2.y*gv.y, hv2.z*gv.z, hv2.w*gv.w));
    ST4(&tms[j][2][d4], make_float4(hv3.x*gv.x, hv3.y*gv.y, hv3.z*gv.z, hv3.w*gv.w));
    __syncwarp();

    // ---- out2 = tm @ Wp2 + o1 @ Wsc2[el] ----
    float4 om0 = {0,0,0,0}, om1 = om0, om2 = om0;
    const float* Ws = Wsc2 + el * 4096;
#pragma unroll 4
    for (int c = 0; c < Cc; c++) {
        float4 wsc = LD4(Ws + c * 64 + d4);
        float4 wp  = LD4(Wp2 + c * 64 + d4);
        fma4(om0, wsc, o1s[j][0][c]);
        fma4(om1, wsc, o1s[j][1][c]);
        fma4(om2, wsc, o1s[j][2][c]);
        fma4(om0, wp, tms[j][0][c]);
        fma4(om1, wp, tms[j][1][c]);
        fma4(om2, wp, tms[j][2][c]);
    }
    ST4(&o2s[j][0][d4], om0);
    ST4(&o2s[j][1][d4], om1);
    ST4(&o2s[j][2][d4], om2);
    __syncwarp();

    // ---- vh[m][q] = out2[m] @ Wv[:, q]  (q <-> h, Hh = 16) ----
    float v0 = 0.0f, v1 = 0.0f, v2 = 0.0f;
#pragma unroll 4
    for (int c = 0; c < Cc; c++) {
        float w = Wv[c * Hh + q];
        v0 = fmaf(o2s[j][0][c], w, v0);
        v1 = fmaf(o2s[j][1][c], w, v1);
        v2 = fmaf(o2s[j][2][c], w, v2);
    }
    vhs[j][0][q] = v0;
    vhs[j][1][q] = v1;
    vhs[j][2][q] = v2;
    invs[j][q] = sqrtf(v0 * v0 + v1 * v1 + v2 * v2 + 1e-12f);
    __syncwarp();

    // ---- gate MLP layer 1 (silu) ----
    float pre = bg1[q];
#pragma unroll
    for (int hh = 0; hh < Hh; hh++)
        pre = fmaf(invs[j][hh], Wg1[hh * Hh + q], pre);
    g1s[j][q] = pre / (1.0f + expf(-pre));
    __syncwarp();

    // ---- gate MLP layer 2 * w_read2 ----
    float a = bg2[q];
#pragma unroll
    for (int hh = 0; hh < Hh; hh++)
        a = fmaf(g1s[j][hh], Wg2[hh * Hh + q], a);
    af[j][q] = a * wread2[q];
    __syncwarp();

    // ---- dipole + per-graph totals ----
    if (q < 3) {
        int m = q;
        float d2 = 0.0f;
#pragma unroll
        for (int h = 0; h < Hh; h++)
            d2 = fmaf(vhs[j][m][h], af[j][h], d2);
        float dip = g_d1[n * 3 + m] + d2;
        out[Gg * 3 + n * 3 + m] = dip;
        int g = batch[n];
        atomicAdd(&out[g * 3 + m], dip + charges[n] * pos[n * 3 + m]);
    }
}

// ---------------------------------------------------------------------------
// Host launcher
// ---------------------------------------------------------------------------
extern "C" void kernel_launch(void* const* d_in, const int* in_sizes, int n_in,
                              void* d_out, int out_size) {
    int iei = -1;
    for (int i = 0; i < n_in; i++) {
        if (in_sizes[i] == 2 * Ee) { iei = i; break; }
    }
    if (iei < 0) iei = 4;

    const float* na      = (const float*)d_in[0];
    const float* pos     = (const float*)d_in[1];
    const float* shifts  = (const float*)d_in[2];
    const float* charges = (const float*)d_in[3];
    const int*   ei      = (const int*)d_in[iei];
    const int*   batch   = (const int*)d_in[iei + 1];

    int w;
    if (iei == 4) {
        w = (n_in > 6 && in_sizes[6] == 1) ? 7 : 6;
    } else {
        w = 4;
    }

    const float* W_embed = (const float*)d_in[w + 0];
    const float* Wr1a    = (const float*)d_in[w + 1];
    const float* Wr1b    = (const float*)d_in[w + 2];
    const float* Wmix1   = (const float*)d_in[w + 3];
    const float* Wsc1    = (const float*)d_in[w + 4];
    const float* Wp1s    = (const float*)d_in[w + 5];
    const float* Wp1v    = (const float*)d_in[w + 6];
    const float* Wp10    = (const float*)d_in[w + 7];
    const float* Wp11    = (const float*)d_in[w + 8];
    const float* wread1  = (const float*)d_in[w + 9];
    const float* Wr2a    = (const float*)d_in[w + 10];
    const float* Wr2b    = (const float*)d_in[w + 11];
    const float* Wmix2   = (const float*)d_in[w + 12];
    const float* Wsc2    = (const float*)d_in[w + 13];
    const float* Wprod2  = (const float*)d_in[w + 14];
    const float* Wp2     = (const float*)d_in[w + 15];
    const float* Wv      = (const float*)d_in[w + 16];
    const float* Wg1     = (const float*)d_in[w + 17];
    const float* bg1     = (const float*)d_in[w + 18];
    const float* Wg2     = (const float*)d_in[w + 19];
    const float* bg2     = (const float*)d_in[w + 20];
    const float* wread2  = (const float*)d_in[w + 21];

    float* out = (float*)d_out;

    k_h0<<<Nn, Cc>>>(na, W_embed, out);
    dim3 tg(TBINS + 1, 2);
    k_table<<<tg, 128>>>(Wr1a, Wr1b, Wr2a, Wr2b);
    k_hist<<<Ee / 256, 256>>>(pos, shifts, ei);
    k_scan<<<1, 1024>>>();
    k_scatter<<<Ee / 256, 256>>>(pos, shifts, ei);
    k_agg<<<Nn, Cc>>>(0);
    k_node1<<<Nn / 4, 64>>>(Wmix1, Wsc1, Wp1s, Wp1v, Wp10, Wp11, wread1);
    k_agg<<<Nn, Cc>>>(1);
    k_node2<<<Nn / 4, 64>>>(Wmix2, Wsc2, Wprod2, Wp2, Wv, Wg1, bg1, Wg2, bg2,
                            wread2, batch, charges, pos, out);
}

// round 10
// speedup vs baseline: 1.5829x; 1.0583x over previous
#include <cuda_runtime.h>
#include <math.h>

// Problem constants (fixed shapes)
#define Nn 8192
#define Ee 131072
#define Cc 64
#define NELn 10
#define NBn 8
#define Gg 32
#define Hh 16
#define RMAXf 5.0f
#define AVGf 16.0f
#define TBINS 2048

// Scratch (device globals; no dynamic allocation allowed)
__device__ __align__(16) float g_h0[Nn * Cc];
__device__ int   g_elem[Nn];
__device__ __align__(16) float g_out0[Nn * Cc];
__device__ __align__(16) float g_out1[Nn * 3 * Cc];
__device__ float g_d1[Nn * 3];
// Radial-MLP lookup tables (lerp over r in [0,RMAX]); 128 outputs per bin,
// pre-scaled by 1/AVG. Layout per bin: [w0(64) | w1(64)].
__device__ __align__(16) float g_tab1[(TBINS + 8) * 128];
__device__ __align__(16) float g_tab2[(TBINS + 8) * 128];
// Edge sort (counting sort by receiver node)
__device__ int    g_deg[Nn];
__device__ int    g_off[Nn + 1];
__device__ int    g_cur[Nn];
__device__ int    g_esnd[Ee];
__device__ float4 g_egeo[Ee];   // (s3*vx/r, s3*vy/r, s3*vz/r, r*TBINS/RMAX)

#define LD4(p) (*(const float4*)(p))
#define ST4(p, v) (*(float4*)(p) = (v))

__device__ __forceinline__ void fma4(float4& acc, float4 w, float s) {
    acc.x = fmaf(w.x, s, acc.x);
    acc.y = fmaf(w.y, s, acc.y);
    acc.z = fmaf(w.z, s, acc.z);
    acc.w = fmaf(w.w, s, acc.w);
}

// ---------------------------------------------------------------------------
// h0 = node_attrs @ W_embed ; elem argmax ; fused init of g_deg and totals.
// ---------------------------------------------------------------------------
__global__ void k_h0(const float* __restrict__ na, const float* __restrict__ We,
                     float* __restrict__ out_tot) {
    int n = blockIdx.x;
    int c = threadIdx.x;
    float acc = 0.0f;
#pragma unroll
    for (int k = 0; k < NELn; k++)
        acc = fmaf(na[n * NELn + k], We[k * Cc + c], acc);
    g_h0[n * Cc + c] = acc;
    if (c == 0) {
        int best = 0;
        float bv = na[n * NELn];
#pragma unroll
        for (int k = 1; k < NELn; k++) {
            float v = na[n * NELn + k];
            if (v > bv) { bv = v; best = k; }
        }
        g_elem[n] = best;
        g_deg[n] = 0;
    }
    if (c == 1 && n < Gg * 3) out_tot[n] = 0.0f;
}

// ---------------------------------------------------------------------------
// Radial-MLP lookup-table build (w(r) smooth in r); scaled by 1/AVG.
// ---------------------------------------------------------------------------
__global__ void k_table(const float* __restrict__ Wa1, const float* __restrict__ Wb1,
                        const float* __restrict__ Wa2, const float* __restrict__ Wb2) {
    int bin  = blockIdx.x;               // 0..TBINS
    int pass = blockIdx.y;
    const float* Wa = pass ? Wa2 : Wa1;
    const float* Wb = pass ? Wb2 : Wb1;
    float* tab      = pass ? g_tab2 : g_tab1;
    int c = threadIdx.x;                 // 0..127

    float r = fmaxf((float)bin * (RMAXf / (float)TBINS), 1e-6f);
    float x = r * (1.0f / RMAXf);
    float x2 = x * x;
    float x5 = x2 * x2 * x;
    float env = 1.0f - 21.0f * x5 + 35.0f * x5 * x - 15.0f * x5 * x2;
    if (x >= 1.0f) env = 0.0f;

    float pref = sqrtf(2.0f / RMAXf) * env / r;
    float wphase = (3.14159265358979323846f / RMAXf) * r;

    __shared__ float hid[Cc];
    if (c < Cc) {
        float h = 0.0f;
#pragma unroll
        for (int nb = 0; nb < NBn; nb++) {
            float rbn = pref * sinf((float)(nb + 1) * wphase);
            h = fmaf(rbn, Wa[nb * Cc + c], h);
        }
        hid[c] = h / (1.0f + expf(-h));
    }
    __syncthreads();

    float acc = 0.0f;
#pragma unroll
    for (int k = 0; k < Cc; k++)
        acc = fmaf(hid[k], Wb[k * 256 + c], acc);
    tab[bin * 128 + c] = acc * (1.0f / AVGf);
}

// ---------------------------------------------------------------------------
// Edge degree histogram (valid edges only: r < RMAX).
// ---------------------------------------------------------------------------
__global__ void k_hist(const float* __restrict__ pos,
                       const float* __restrict__ shifts,
                       const int* __restrict__ ei) {
    int e = blockIdx.x * blockDim.x + threadIdx.x;
    if (e >= Ee) return;
    int snd = ei[e];
    int rcv = ei[Ee + e];
    float vx = pos[rcv * 3 + 0] - pos[snd * 3 + 0] + shifts[e * 3 + 0];
    float vy = pos[rcv * 3 + 1] - pos[snd * 3 + 1] + shifts[e * 3 + 1];
    float vz = pos[rcv * 3 + 2] - pos[snd * 3 + 2] + shifts[e * 3 + 2];
    float r  = sqrtf(vx * vx + vy * vy + vz * vz + 1e-12f);
    if (r < RMAXf) atomicAdd(&g_deg[rcv], 1);
}

// ---------------------------------------------------------------------------
// Exclusive prefix sum over 8192 degrees: shuffle-based, 2 block barriers.
// ---------------------------------------------------------------------------
__global__ void k_scan() {
    __shared__ int wsum[32];
    int t = threadIdx.x;
    int lane = t & 31, wid = t >> 5;

    int v[8];
    int sum = 0;
#pragma unroll
    for (int j = 0; j < 8; j++) { v[j] = g_deg[t * 8 + j]; sum += v[j]; }

    // inclusive warp scan of per-thread sums
    int x = sum;
#pragma unroll
    for (int o = 1; o < 32; o <<= 1) {
        int y = __shfl_up_sync(0xffffffffu, x, o);
        if (lane >= o) x += y;
    }
    if (lane == 31) wsum[wid] = x;
    __syncthreads();
    if (wid == 0) {
        int w = wsum[lane];
#pragma unroll
        for (int o = 1; o < 32; o <<= 1) {
            int y = __shfl_up_sync(0xffffffffu, w, o);
            if (lane >= o) w += y;
        }
        wsum[lane] = w;
    }
    __syncthreads();

    int excl = x - sum + (wid > 0 ? wsum[wid - 1] : 0);
#pragma unroll
    for (int j = 0; j < 8; j++) {
        g_off[t * 8 + j] = excl;
        g_cur[t * 8 + j] = excl;
        excl += v[j];
    }
    if (t == 1023) g_off[Nn] = excl;
}

// ---------------------------------------------------------------------------
// Scatter edge payload (geometry computed ONCE, reused by both passes).
// ---------------------------------------------------------------------------
__global__ void k_scatter(const float* __restrict__ pos,
                          const float* __restrict__ shifts,
                          const int* __restrict__ ei) {
    int e = blockIdx.x * blockDim.x + threadIdx.x;
    if (e >= Ee) return;
    int snd = ei[e];
    int rcv = ei[Ee + e];
    float vx = pos[rcv * 3 + 0] - pos[snd * 3 + 0] + shifts[e * 3 + 0];
    float vy = pos[rcv * 3 + 1] - pos[snd * 3 + 1] + shifts[e * 3 + 1];
    float vz = pos[rcv * 3 + 2] - pos[snd * 3 + 2] + shifts[e * 3 + 2];
    float r  = sqrtf(vx * vx + vy * vy + vz * vz + 1e-12f);
    if (r >= RMAXf) return;
    int p = atomicAdd(&g_cur[rcv], 1);
    const float s3 = 1.7320508075688772f;
    float inv = s3 / r;
    g_esnd[p] = snd;
    g_egeo[p] = make_float4(vx * inv, vy * inv, vz * inv,
                            r * ((float)TBINS / RMAXf));
}

// ---------------------------------------------------------------------------
// Fused gather for one node's edge segment: 16 lanes x 4 channels (float4).
// Accumulates A[k] (pre-scaled by 1/AVG via the table) into 4 float4 regs
// and stores them to the smem tile As[j][k][*].
// ---------------------------------------------------------------------------
__device__ __forceinline__ void gather16(
        int n, int j, int d4,
        const float* __restrict__ feat,
        const float* __restrict__ tab,
        float (*As)[4][Cc])
{
    int s = g_off[n];
    int e = g_off[n + 1];
    float4 a0 = {0,0,0,0}, a1 = a0, a2 = a0, a3 = a0;

    for (int p = s; p < e; p++) {
        int snd = g_esnd[p];          // broadcast within the 16-lane group
        float4 gv = g_egeo[p];        // broadcast
        float tt = gv.w;
        int   i = (int)tt;
        float f = tt - (float)i;
        const float* row = tab + i * 128;
        float4 w0a = LD4(row + d4);
        float4 w0b = LD4(row + 128 + d4);
        float4 w1a = LD4(row + 64 + d4);
        float4 w1b = LD4(row + 192 + d4);
        float4 fs  = LD4(feat + snd * Cc + d4);

        float4 w0, w1;
        w0.x = w0a.x + (w0b.x - w0a.x) * f;
        w0.y = w0a.y + (w0b.y - w0a.y) * f;
        w0.z = w0a.z + (w0b.z - w0a.z) * f;
        w0.w = w0a.w + (w0b.w - w0a.w) * f;
        w1.x = w1a.x + (w1b.x - w1a.x) * f;
        w1.y = w1a.y + (w1b.y - w1a.y) * f;
        w1.z = w1a.z + (w1b.z - w1a.z) * f;
        w1.w = w1a.w + (w1b.w - w1a.w) * f;

        a0.x = fmaf(fs.x, w0.x, a0.x);
        a0.y = fmaf(fs.y, w0.y, a0.y);
        a0.z = fmaf(fs.z, w0.z, a0.z);
        a0.w = fmaf(fs.w, w0.w, a0.w);

        float4 g;
        g.x = fs.x * w1.x;
        g.y = fs.y * w1.y;
        g.z = fs.z * w1.z;
        g.w = fs.w * w1.w;

        a1.x = fmaf(g.x, gv.x, a1.x);
        a1.y = fmaf(g.y, gv.x, a1.y);
        a1.z = fmaf(g.z, gv.x, a1.z);
        a1.w = fmaf(g.w, gv.x, a1.w);
        a2.x = fmaf(g.x, gv.y, a2.x);
        a2.y = fmaf(g.y, gv.y, a2.y);
        a2.z = fmaf(g.z, gv.y, a2.z);
        a2.w = fmaf(g.w, gv.y, a2.w);
        a3.x = fmaf(g.x, gv.z, a3.x);
        a3.y = fmaf(g.y, gv.z, a3.y);
        a3.z = fmaf(g.z, gv.z, a3.z);
        a3.w = fmaf(g.w, gv.z, a3.w);
    }

    ST4(&As[j][0][d4], a0);
    ST4(&As[j][1][d4], a1);
    ST4(&As[j][2][d4], a2);
    ST4(&As[j][3][d4], a3);
}

// ---------------------------------------------------------------------------
// Node layer 1 (fused with aggregation pass 1).
// 64 threads = 4 nodes x 16 lanes; each thread owns 4 channels (float4).
// ---------------------------------------------------------------------------
__global__ void __launch_bounds__(64) k_node1(
        const float* __restrict__ Wmix1,
        const float* __restrict__ Wsc1,
        const float* __restrict__ Wps,
        const float* __restrict__ Wpv,
        const float* __restrict__ Wp10,
        const float* __restrict__ Wp11,
        const float* __restrict__ wread1)
{
    int t = threadIdx.x;
    int j = t >> 4;          // node in block (0..3)
    int q = t & 15;          // channel quad (0..15)
    int d4 = q << 2;
    int n = blockIdx.x * 4 + j;

    __shared__ float As[4][4][Cc];
    __shared__ float h0s[4][Cc];
    __shared__ float m0s[4][Cc];
    __shared__ float tms[4][3][Cc];

    // ---- fused aggregation (pass 1: feat = h0) ----
    gather16(n, j, d4, g_h0, g_tab1, As);
    ST4(&h0s[j][d4], LD4(g_h0 + n * 64 + d4));
    __syncwarp();

    // ---- h1[k][d] = sum_c A[k][c] * Wmix[LOF[k]][c][d]  (LOF = 0,1,1,1) ----
    float4 hv0 = {0,0,0,0}, hv1 = hv0, hv2 = hv0, hv3 = hv0;
#pragma unroll 4
    for (int c = 0; c < Cc; c++) {
        float4 w0 = LD4(Wmix1 + c * 64 + d4);
        float4 w1 = LD4(Wmix1 + 4096 + c * 64 + d4);
        fma4(hv0, w0, As[j][0][c]);
        fma4(hv1, w1, As[j][1][c]);
        fma4(hv2, w1, As[j][2][c]);
        fma4(hv3, w1, As[j][3][c]);
    }

    // ---- polynomial gates ----
    int el = g_elem[n];
    float4 ws0 = LD4(Wps + el * 64 + d4);
    float4 ws1 = LD4(Wps + NELn * 64 + el * 64 + d4);
    float4 ws2 = LD4(Wps + 2 * NELn * 64 + el * 64 + d4);
    float4 wv0 = LD4(Wpv + el * 64 + d4);
    float4 wv1 = LD4(Wpv + NELn * 64 + el * 64 + d4);
    float4 wv2 = LD4(Wpv + 2 * NELn * 64 + el * 64 + d4);

    float4 m0, gv;
    m0.x = hv0.x * (ws0.x + hv0.x * (ws1.x + hv0.x * ws2.x));
    m0.y = hv0.y * (ws0.y + hv0.y * (ws1.y + hv0.y * ws2.y));
    m0.z = hv0.z * (ws0.z + hv0.z * (ws1.z + hv0.z * ws2.z));
    m0.w = hv0.w * (ws0.w + hv0.w * (ws1.w + hv0.w * ws2.w));
    gv.x = wv0.x + hv0.x * (wv1.x + hv0.x * wv2.x);
    gv.y = wv0.y + hv0.y * (wv1.y + hv0.y * wv2.y);
    gv.z = wv0.z + hv0.z * (wv1.z + hv0.z * wv2.z);
    gv.w = wv0.w + hv0.w * (wv1.w + hv0.w * wv2.w);

    ST4(&m0s[j][d4], m0);
    ST4(&tms[j][0][d4], make_float4(hv1.x*gv.x, hv1.y*gv.y, hv1.z*gv.z, hv1.w*gv.w));
    ST4(&tms[j][1][d4], make_float4(hv2.x*gv.x, hv2.y*gv.y, hv2.z*gv.z, hv2.w*gv.w));
    ST4(&tms[j][2][d4], make_float4(hv3.x*gv.x, hv3.y*gv.y, hv3.z*gv.z, hv3.w*gv.w));
    __syncwarp();

    // ---- out0 = m0 @ Wp1_0 + h0 @ Wsc1[el] ----
    float4 o0 = {0,0,0,0};
    const float* Ws = Wsc1 + el * 4096;
#pragma unroll 4
    for (int c = 0; c < Cc; c++) {
        float4 wsc = LD4(Ws + c * 64 + d4);
        float4 wp  = LD4(Wp10 + c * 64 + d4);
        fma4(o0, wsc, h0s[j][c]);
        fma4(o0, wp,  m0s[j][c]);
    }
    ST4(g_out0 + n * 64 + d4, o0);

    // ---- out1 = tm @ Wp1_1 ; d1 = out1 . w_read1 ----
    float4 om0 = {0,0,0,0}, om1 = om0, om2 = om0;
#pragma unroll 4
    for (int c = 0; c < Cc; c++) {
        float4 wp = LD4(Wp11 + c * 64 + d4);
        fma4(om0, wp, tms[j][0][c]);
        fma4(om1, wp, tms[j][1][c]);
        fma4(om2, wp, tms[j][2][c]);
    }
    ST4(g_out1 + (n * 3 + 0) * 64 + d4, om0);
    ST4(g_out1 + (n * 3 + 1) * 64 + d4, om1);
    ST4(g_out1 + (n * 3 + 2) * 64 + d4, om2);

    float4 wrv = LD4(wread1 + d4);
#pragma unroll
    for (int m = 0; m < 3; m++) {
        float4 o = (m == 0) ? om0 : ((m == 1) ? om1 : om2);
        float v = o.x * wrv.x + o.y * wrv.y + o.z * wrv.z + o.w * wrv.w;
        v += __shfl_down_sync(0xffffffffu, v, 8);
        v += __shfl_down_sync(0xffffffffu, v, 4);
        v += __shfl_down_sync(0xffffffffu, v, 2);
        v += __shfl_down_sync(0xffffffffu, v, 1);
        if (q == 0) g_d1[n * 3 + m] = v;
    }
}

// ---------------------------------------------------------------------------
// Node layer 2 (fused with aggregation pass 2). Same layout.
// ---------------------------------------------------------------------------
__global__ void __launch_bounds__(64) k_node2(
        const float* __restrict__ Wmix2,
        const float* __restrict__ Wsc2,
        const float* __restrict__ Wprod2,
        const float* __restrict__ Wp2,
        const float* __restrict__ Wv,
        const float* __restrict__ Wg1,
        const float* __restrict__ bg1,
        const float* __restrict__ Wg2,
        const float* __restrict__ bg2,
        const float* __restrict__ wread2,
        const int* __restrict__ batch,
        const float* __restrict__ charges,
        const float* __restrict__ pos,
        float* __restrict__ out)
{
    int t = threadIdx.x;
    int j = t >> 4;
    int q = t & 15;
    int d4 = q << 2;
    int n = blockIdx.x * 4 + j;

    __shared__ float As[4][4][Cc];
    __shared__ float o1s[4][3][Cc];
    __shared__ float tms[4][3][Cc];
    __shared__ float o2s[4][3][Cc];
    __shared__ float vhs[4][3][Hh];
    __shared__ float invs[4][Hh];
    __shared__ float g1s[4][Hh];
    __shared__ float af[4][Hh];

    // ---- fused aggregation (pass 2: feat = out0) ----
    gather16(n, j, d4, g_out0, g_tab2, As);
#pragma unroll
    for (int m = 0; m < 3; m++)
        ST4(&o1s[j][m][d4], LD4(g_out1 + (n * 3 + m) * 64 + d4));
    __syncwarp();

    // ---- h2 ----
    float4 hv0 = {0,0,0,0}, hv1 = hv0, hv2 = hv0, hv3 = hv0;
#pragma unroll 4
    for (int c = 0; c < Cc; c++) {
        float4 w0 = LD4(Wmix2 + c * 64 + d4);
        float4 w1 = LD4(Wmix2 + 4096 + c * 64 + d4);
        fma4(hv0, w0, As[j][0][c]);
        fma4(hv1, w1, As[j][1][c]);
        fma4(hv2, w1, As[j][2][c]);
        fma4(hv3, w1, As[j][3][c]);
    }

    int el = g_elem[n];
    float4 wv0 = LD4(Wprod2 + el * 64 + d4);
    float4 wv1 = LD4(Wprod2 + NELn * 64 + el * 64 + d4);
    float4 wv2 = LD4(Wprod2 + 2 * NELn * 64 + el * 64 + d4);
    float4 gv;
    gv.x = wv0.x + hv0.x * (wv1.x + hv0.x * wv2.x);
    gv.y = wv0.y + hv0.y * (wv1.y + hv0.y * wv2.y);
    gv.z = wv0.z + hv0.z * (wv1.z + hv0.z * wv2.z);
    gv.w = wv0.w + hv0.w * (wv1.w + hv0.w * wv2.w);

    ST4(&tms[j][0][d4], make_float4(hv1.x*gv.x, hv1.y*gv.y, hv1.z*gv.z, hv1.w*gv.w));
    ST4(&tms[j][1][d4], make_float4(hv2.x*gv.x, hv2.y*gv.y, hv2.z*gv.z, hv2.w*gv.w));
    ST4(&tms[j][2][d4], make_float4(hv3.x*gv.x, hv3.y*gv.y, hv3.z*gv.z, hv3.w*gv.w));
    __syncwarp();

    // ---- out2 = tm @ Wp2 + o1 @ Wsc2[el] ----
    float4 om0 = {0,0,0,0}, om1 = om0, om2 = om0;
    const float* Ws = Wsc2 + el * 4096;
#pragma unroll 4
    for (int c = 0; c < Cc; c++) {
        float4 wsc = LD4(Ws + c * 64 + d4);
        float4 wp  = LD4(Wp2 + c * 64 + d4);
        fma4(om0, wsc, o1s[j][0][c]);
        fma4(om1, wsc, o1s[j][1][c]);
        fma4(om2, wsc, o1s[j][2][c]);
        fma4(om0, wp, tms[j][0][c]);
        fma4(om1, wp, tms[j][1][c]);
        fma4(om2, wp, tms[j][2][c]);
    }
    ST4(&o2s[j][0][d4], om0);
    ST4(&o2s[j][1][d4], om1);
    ST4(&o2s[j][2][d4], om2);
    __syncwarp();

    // ---- vh[m][q] = out2[m] @ Wv[:, q]  (q <-> h, Hh = 16) ----
    float v0 = 0.0f, v1 = 0.0f, v2 = 0.0f;
#pragma unroll 4
    for (int c = 0; c < Cc; c++) {
        float w = Wv[c * Hh + q];
        v0 = fmaf(o2s[j][0][c], w, v0);
        v1 = fmaf(o2s[j][1][c], w, v1);
        v2 = fmaf(o2s[j][2][c], w, v2);
    }
    vhs[j][0][q] = v0;
    vhs[j][1][q] = v1;
    vhs[j][2][q] = v2;
    invs[j][q] = sqrtf(v0 * v0 + v1 * v1 + v2 * v2 + 1e-12f);
    __syncwarp();

    // ---- gate MLP layer 1 (silu) ----
    float pre = bg1[q];
#pragma unroll
    for (int hh = 0; hh < Hh; hh++)
        pre = fmaf(invs[j][hh], Wg1[hh * Hh + q], pre);
    g1s[j][q] = pre / (1.0f + expf(-pre));
    __syncwarp();

    // ---- gate MLP layer 2 * w_read2 ----
    float a = bg2[q];
#pragma unroll
    for (int hh = 0; hh < Hh; hh++)
        a = fmaf(g1s[j][hh], Wg2[hh * Hh + q], a);
    af[j][q] = a * wread2[q];
    __syncwarp();

    // ---- dipole + per-graph totals ----
    if (q < 3) {
        int m = q;
        float d2 = 0.0f;
#pragma unroll
        for (int h = 0; h < Hh; h++)
            d2 = fmaf(vhs[j][m][h], af[j][h], d2);
        float dip = g_d1[n * 3 + m] + d2;
        out[Gg * 3 + n * 3 + m] = dip;
        int g = batch[n];
        atomicAdd(&out[g * 3 + m], dip + charges[n] * pos[n * 3 + m]);
    }
}

// ---------------------------------------------------------------------------
// Host launcher
// ---------------------------------------------------------------------------
extern "C" void kernel_launch(void* const* d_in, const int* in_sizes, int n_in,
                              void* d_out, int out_size) {
    int iei = -1;
    for (int i = 0; i < n_in; i++) {
        if (in_sizes[i] == 2 * Ee) { iei = i; break; }
    }
    if (iei < 0) iei = 4;

    const float* na      = (const float*)d_in[0];
    const float* pos     = (const float*)d_in[1];
    const float* shifts  = (const float*)d_in[2];
    const float* charges = (const float*)d_in[3];
    const int*   ei      = (const int*)d_in[iei];
    const int*   batch   = (const int*)d_in[iei + 1];

    int w;
    if (iei == 4) {
        w = (n_in > 6 && in_sizes[6] == 1) ? 7 : 6;
    } else {
        w = 4;
    }

    const float* W_embed = (const float*)d_in[w + 0];
    const float* Wr1a    = (const float*)d_in[w + 1];
    const float* Wr1b    = (const float*)d_in[w + 2];
    const float* Wmix1   = (const float*)d_in[w + 3];
    const float* Wsc1    = (const float*)d_in[w + 4];
    const float* Wp1s    = (const float*)d_in[w + 5];
    const float* Wp1v    = (const float*)d_in[w + 6];
    const float* Wp10    = (const float*)d_in[w + 7];
    const float* Wp11    = (const float*)d_in[w + 8];
    const float* wread1  = (const float*)d_in[w + 9];
    const float* Wr2a    = (const float*)d_in[w + 10];
    const float* Wr2b    = (const float*)d_in[w + 11];
    const float* Wmix2   = (const float*)d_in[w + 12];
    const float* Wsc2    = (const float*)d_in[w + 13];
    const float* Wprod2  = (const float*)d_in[w + 14];
    const float* Wp2     = (const float*)d_in[w + 15];
    const float* Wv      = (const float*)d_in[w + 16];
    const float* Wg1     = (const float*)d_in[w + 17];
    const float* bg1     = (const float*)d_in[w + 18];
    const float* Wg2     = (const float*)d_in[w + 19];
    const float* bg2     = (const float*)d_in[w + 20];
    const float* wread2  = (const float*)d_in[w + 21];

    float* out = (float*)d_out;

    k_h0<<<Nn, Cc>>>(na, W_embed, out);
    dim3 tg(TBINS + 1, 2);
    k_table<<<tg, 128>>>(Wr1a, Wr1b, Wr2a, Wr2b);
    k_hist<<<Ee / 256, 256>>>(pos, shifts, ei);
    k_scan<<<1, 1024>>>();
    k_scatter<<<Ee / 256, 256>>>(pos, shifts, ei);
    k_node1<<<Nn / 4, 64>>>(Wmix1, Wsc1, Wp1s, Wp1v, Wp10, Wp11, wread1);
    k_node2<<<Nn / 4, 64>>>(Wmix2, Wsc2, Wprod2, Wp2, Wv, Wg1, bg1, Wg2, bg2,
                            wread2, batch, charges, pos, out);
}

// round 11
// speedup vs baseline: 1.7882x; 1.1297x over previous
#include <cuda_runtime.h>
#include <math.h>

// Problem constants (fixed shapes)
#define Nn 8192
#define Ee 131072
#define Cc 64
#define NELn 10
#define NBn 8
#define Gg 32
#define Hh 16
#define RMAXf 5.0f
#define AVGf 16.0f
#define TBINS 2048
#define CAP 128   // per-node edge-bucket capacity (deg ~ Poisson(16); P(>=128)~0)

// Scratch (device globals; no dynamic allocation allowed)
__device__ __align__(16) float g_h0[Nn * Cc];
__device__ int   g_elem[Nn];
__device__ __align__(16) float g_out0[Nn * Cc];
__device__ __align__(16) float g_out1[Nn * 3 * Cc];
__device__ float g_d1[Nn * 3];
// Radial-MLP lookup tables (lerp over r in [0,RMAX]); 128 outputs per bin,
// pre-scaled by 1/AVG. Layout per bin: [w0(64) | w1(64)].
__device__ __align__(16) float g_tab1[(TBINS + 8) * 128];
__device__ __align__(16) float g_tab2[(TBINS + 8) * 128];
// Fixed-capacity edge buckets (no histogram / prefix scan needed)
__device__ int    g_cur[Nn];                 // per-node valid-edge count
__device__ int    g_esnd[Nn * CAP];
__device__ float4 g_egeo[Nn * CAP];          // (s3*vx/r, s3*vy/r, s3*vz/r, r*TBINS/RMAX)

#define LD4(p) (*(const float4*)(p))
#define ST4(p, v) (*(float4*)(p) = (v))

__device__ __forceinline__ void fma4(float4& acc, float4 w, float s) {
    acc.x = fmaf(w.x, s, acc.x);
    acc.y = fmaf(w.y, s, acc.y);
    acc.z = fmaf(w.z, s, acc.z);
    acc.w = fmaf(w.w, s, acc.w);
}

// ---------------------------------------------------------------------------
// h0 = node_attrs @ W_embed ; elem argmax ; fused init of g_cur and totals.
// ---------------------------------------------------------------------------
__global__ void k_h0(const float* __restrict__ na, const float* __restrict__ We,
                     float* __restrict__ out_tot) {
    int n = blockIdx.x;
    int c = threadIdx.x;
    float acc = 0.0f;
#pragma unroll
    for (int k = 0; k < NELn; k++)
        acc = fmaf(na[n * NELn + k], We[k * Cc + c], acc);
    g_h0[n * Cc + c] = acc;
    if (c == 0) {
        int best = 0;
        float bv = na[n * NELn];
#pragma unroll
        for (int k = 1; k < NELn; k++) {
            float v = na[n * NELn + k];
            if (v > bv) { bv = v; best = k; }
        }
        g_elem[n] = best;
        g_cur[n] = 0;
    }
    if (c == 1 && n < Gg * 3) out_tot[n] = 0.0f;
}

// ---------------------------------------------------------------------------
// Radial-MLP lookup-table build (w(r) smooth in r); scaled by 1/AVG.
// ---------------------------------------------------------------------------
__global__ void k_table(const float* __restrict__ Wa1, const float* __restrict__ Wb1,
                        const float* __restrict__ Wa2, const float* __restrict__ Wb2) {
    int bin  = blockIdx.x;               // 0..TBINS
    int pass = blockIdx.y;
    const float* Wa = pass ? Wa2 : Wa1;
    const float* Wb = pass ? Wb2 : Wb1;
    float* tab      = pass ? g_tab2 : g_tab1;
    int c = threadIdx.x;                 // 0..127

    float r = fmaxf((float)bin * (RMAXf / (float)TBINS), 1e-6f);
    float x = r * (1.0f / RMAXf);
    float x2 = x * x;
    float x5 = x2 * x2 * x;
    float env = 1.0f - 21.0f * x5 + 35.0f * x5 * x - 15.0f * x5 * x2;
    if (x >= 1.0f) env = 0.0f;

    float pref = sqrtf(2.0f / RMAXf) * env / r;
    float wphase = (3.14159265358979323846f / RMAXf) * r;

    __shared__ float hid[Cc];
    if (c < Cc) {
        float h = 0.0f;
#pragma unroll
        for (int nb = 0; nb < NBn; nb++) {
            float rbn = pref * sinf((float)(nb + 1) * wphase);
            h = fmaf(rbn, Wa[nb * Cc + c], h);
        }
        hid[c] = h / (1.0f + expf(-h));
    }
    __syncthreads();

    float acc = 0.0f;
#pragma unroll
    for (int k = 0; k < Cc; k++)
        acc = fmaf(hid[k], Wb[k * 256 + c], acc);
    tab[bin * 128 + c] = acc * (1.0f / AVGf);
}

// ---------------------------------------------------------------------------
// Scatter edge payload into fixed-capacity per-receiver buckets.
// Geometry computed ONCE, reused by both message-passing passes.
// ---------------------------------------------------------------------------
__global__ void k_scatter(const float* __restrict__ pos,
                          const float* __restrict__ shifts,
                          const int* __restrict__ ei) {
    int e = blockIdx.x * blockDim.x + threadIdx.x;
    if (e >= Ee) return;
    int snd = ei[e];
    int rcv = ei[Ee + e];
    float vx = pos[rcv * 3 + 0] - pos[snd * 3 + 0] + shifts[e * 3 + 0];
    float vy = pos[rcv * 3 + 1] - pos[snd * 3 + 1] + shifts[e * 3 + 1];
    float vz = pos[rcv * 3 + 2] - pos[snd * 3 + 2] + shifts[e * 3 + 2];
    float r  = sqrtf(vx * vx + vy * vy + vz * vz + 1e-12f);
    if (r >= RMAXf) return;
    int slot = atomicAdd(&g_cur[rcv], 1);
    if (slot >= CAP) return;   // statistically unreachable guard
    int p = rcv * CAP + slot;
    const float s3 = 1.7320508075688772f;
    float inv = s3 / r;
    g_esnd[p] = snd;
    g_egeo[p] = make_float4(vx * inv, vy * inv, vz * inv,
                            r * ((float)TBINS / RMAXf));
}

// ---------------------------------------------------------------------------
// Fused gather for one node's edge bucket: 16 lanes x 4 channels (float4).
// Accumulates A[k] (pre-scaled by 1/AVG via the table) into 4 float4 regs
// and stores them to the smem tile As[j][k][*].
// ---------------------------------------------------------------------------
__device__ __forceinline__ void gather16(
        int n, int j, int d4,
        const float* __restrict__ feat,
        const float* __restrict__ tab,
        float (*As)[4][Cc])
{
    int s = n * CAP;
    int e = s + min(g_cur[n], CAP);
    float4 a0 = {0,0,0,0}, a1 = a0, a2 = a0, a3 = a0;

    for (int p = s; p < e; p++) {
        int snd = g_esnd[p];          // broadcast within the 16-lane group
        float4 gv = g_egeo[p];        // broadcast
        float tt = gv.w;
        int   i = (int)tt;
        float f = tt - (float)i;
        const float* row = tab + i * 128;
        float4 w0a = LD4(row + d4);
        float4 w0b = LD4(row + 128 + d4);
        float4 w1a = LD4(row + 64 + d4);
        float4 w1b = LD4(row + 192 + d4);
        float4 fs  = LD4(feat + snd * Cc + d4);

        float4 w0, w1;
        w0.x = w0a.x + (w0b.x - w0a.x) * f;
        w0.y = w0a.y + (w0b.y - w0a.y) * f;
        w0.z = w0a.z + (w0b.z - w0a.z) * f;
        w0.w = w0a.w + (w0b.w - w0a.w) * f;
        w1.x = w1a.x + (w1b.x - w1a.x) * f;
        w1.y = w1a.y + (w1b.y - w1a.y) * f;
        w1.z = w1a.z + (w1b.z - w1a.z) * f;
        w1.w = w1a.w + (w1b.w - w1a.w) * f;

        a0.x = fmaf(fs.x, w0.x, a0.x);
        a0.y = fmaf(fs.y, w0.y, a0.y);
        a0.z = fmaf(fs.z, w0.z, a0.z);
        a0.w = fmaf(fs.w, w0.w, a0.w);

        float4 g;
        g.x = fs.x * w1.x;
        g.y = fs.y * w1.y;
        g.z = fs.z * w1.z;
        g.w = fs.w * w1.w;

        a1.x = fmaf(g.x, gv.x, a1.x);
        a1.y = fmaf(g.y, gv.x, a1.y);
        a1.z = fmaf(g.z, gv.x, a1.z);
        a1.w = fmaf(g.w, gv.x, a1.w);
        a2.x = fmaf(g.x, gv.y, a2.x);
        a2.y = fmaf(g.y, gv.y, a2.y);
        a2.z = fmaf(g.z, gv.y, a2.z);
        a2.w = fmaf(g.w, gv.y, a2.w);
        a3.x = fmaf(g.x, gv.z, a3.x);
        a3.y = fmaf(g.y, gv.z, a3.y);
        a3.z = fmaf(g.z, gv.z, a3.z);
        a3.w = fmaf(g.w, gv.z, a3.w);
    }

    ST4(&As[j][0][d4], a0);
    ST4(&As[j][1][d4], a1);
    ST4(&As[j][2][d4], a2);
    ST4(&As[j][3][d4], a3);
}

// ---------------------------------------------------------------------------
// Node layer 1 (fused with aggregation pass 1).
// 64 threads = 4 nodes x 16 lanes; each thread owns 4 channels (float4).
// ---------------------------------------------------------------------------
__global__ void __launch_bounds__(64) k_node1(
        const float* __restrict__ Wmix1,
        const float* __restrict__ Wsc1,
        const float* __restrict__ Wps,
        const float* __restrict__ Wpv,
        const float* __restrict__ Wp10,
        const float* __restrict__ Wp11,
        const float* __restrict__ wread1)
{
    int t = threadIdx.x;
    int j = t >> 4;          // node in block (0..3)
    int q = t & 15;          // channel quad (0..15)
    int d4 = q << 2;
    int n = blockIdx.x * 4 + j;

    __shared__ float As[4][4][Cc];
    __shared__ float h0s[4][Cc];
    __shared__ float m0s[4][Cc];
    __shared__ float tms[4][3][Cc];

    // ---- fused aggregation (pass 1: feat = h0) ----
    gather16(n, j, d4, g_h0, g_tab1, As);
    ST4(&h0s[j][d4], LD4(g_h0 + n * 64 + d4));
    __syncwarp();

    // ---- h1[k][d] = sum_c A[k][c] * Wmix[LOF[k]][c][d]  (LOF = 0,1,1,1) ----
    float4 hv0 = {0,0,0,0}, hv1 = hv0, hv2 = hv0, hv3 = hv0;
#pragma unroll 4
    for (int c = 0; c < Cc; c++) {
        float4 w0 = LD4(Wmix1 + c * 64 + d4);
        float4 w1 = LD4(Wmix1 + 4096 + c * 64 + d4);
        fma4(hv0, w0, As[j][0][c]);
        fma4(hv1, w1, As[j][1][c]);
        fma4(hv2, w1, As[j][2][c]);
        fma4(hv3, w1, As[j][3][c]);
    }

    // ---- polynomial gates ----
    int el = g_elem[n];
    float4 ws0 = LD4(Wps + el * 64 + d4);
    float4 ws1 = LD4(Wps + NELn * 64 + el * 64 + d4);
    float4 ws2 = LD4(Wps + 2 * NELn * 64 + el * 64 + d4);
    float4 wv0 = LD4(Wpv + el * 64 + d4);
    float4 wv1 = LD4(Wpv + NELn * 64 + el * 64 + d4);
    float4 wv2 = LD4(Wpv + 2 * NELn * 64 + el * 64 + d4);

    float4 m0, gv;
    m0.x = hv0.x * (ws0.x + hv0.x * (ws1.x + hv0.x * ws2.x));
    m0.y = hv0.y * (ws0.y + hv0.y * (ws1.y + hv0.y * ws2.y));
    m0.z = hv0.z * (ws0.z + hv0.z * (ws1.z + hv0.z * ws2.z));
    m0.w = hv0.w * (ws0.w + hv0.w * (ws1.w + hv0.w * ws2.w));
    gv.x = wv0.x + hv0.x * (wv1.x + hv0.x * wv2.x);
    gv.y = wv0.y + hv0.y * (wv1.y + hv0.y * wv2.y);
    gv.z = wv0.z + hv0.z * (wv1.z + hv0.z * wv2.z);
    gv.w = wv0.w + hv0.w * (wv1.w + hv0.w * wv2.w);

    ST4(&m0s[j][d4], m0);
    ST4(&tms[j][0][d4], make_float4(hv1.x*gv.x, hv1.y*gv.y, hv1.z*gv.z, hv1.w*gv.w));
    ST4(&tms[j][1][d4], make_float4(hv2.x*gv.x, hv2.y*gv.y, hv2.z*gv.z, hv2.w*gv.w));
    ST4(&tms[j][2][d4], make_float4(hv3.x*gv.x, hv3.y*gv.y, hv3.z*gv.z, hv3.w*gv.w));
    __syncwarp();

    // ---- out0 = m0 @ Wp1_0 + h0 @ Wsc1[el] ----
    float4 o0 = {0,0,0,0};
    const float* Ws = Wsc1 + el * 4096;
#pragma unroll 4
    for (int c = 0; c < Cc; c++) {
        float4 wsc = LD4(Ws + c * 64 + d4);
        float4 wp  = LD4(Wp10 + c * 64 + d4);
        fma4(o0, wsc, h0s[j][c]);
        fma4(o0, wp,  m0s[j][c]);
    }
    ST4(g_out0 + n * 64 + d4, o0);

    // ---- out1 = tm @ Wp1_1 ; d1 = out1 . w_read1 ----
    float4 om0 = {0,0,0,0}, om1 = om0, om2 = om0;
#pragma unroll 4
    for (int c = 0; c < Cc; c++) {
        float4 wp = LD4(Wp11 + c * 64 + d4);
        fma4(om0, wp, tms[j][0][c]);
        fma4(om1, wp, tms[j][1][c]);
        fma4(om2, wp, tms[j][2][c]);
    }
    ST4(g_out1 + (n * 3 + 0) * 64 + d4, om0);
    ST4(g_out1 + (n * 3 + 1) * 64 + d4, om1);
    ST4(g_out1 + (n * 3 + 2) * 64 + d4, om2);

    float4 wrv = LD4(wread1 + d4);
#pragma unroll
    for (int m = 0; m < 3; m++) {
        float4 o = (m == 0) ? om0 : ((m == 1) ? om1 : om2);
        float v = o.x * wrv.x + o.y * wrv.y + o.z * wrv.z + o.w * wrv.w;
        v += __shfl_down_sync(0xffffffffu, v, 8);
        v += __shfl_down_sync(0xffffffffu, v, 4);
        v += __shfl_down_sync(0xffffffffu, v, 2);
        v += __shfl_down_sync(0xffffffffu, v, 1);
        if (q == 0) g_d1[n * 3 + m] = v;
    }
}

// ---------------------------------------------------------------------------
// Node layer 2 (fused with aggregation pass 2). Same layout.
// ---------------------------------------------------------------------------
__global__ void __launch_bounds__(64) k_node2(
        const float* __restrict__ Wmix2,
        const float* __restrict__ Wsc2,
        const float* __restrict__ Wprod2,
        const float* __restrict__ Wp2,
        const float* __restrict__ Wv,
        const float* __restrict__ Wg1,
        const float* __restrict__ bg1,
        const float* __restrict__ Wg2,
        const float* __restrict__ bg2,
        const float* __restrict__ wread2,
        const int* __restrict__ batch,
        const float* __restrict__ charges,
        const float* __restrict__ pos,
        float* __restrict__ out)
{
    int t = threadIdx.x;
    int j = t >> 4;
    int q = t & 15;
    int d4 = q << 2;
    int n = blockIdx.x * 4 + j;

    __shared__ float As[4][4][Cc];
    __shared__ float o1s[4][3][Cc];
    __shared__ float tms[4][3][Cc];
    __shared__ float o2s[4][3][Cc];
    __shared__ float vhs[4][3][Hh];
    __shared__ float invs[4][Hh];
    __shared__ float g1s[4][Hh];
    __shared__ float af[4][Hh];

    // ---- fused aggregation (pass 2: feat = out0) ----
    gather16(n, j, d4, g_out0, g_tab2, As);
#pragma unroll
    for (int m = 0; m < 3; m++)
        ST4(&o1s[j][m][d4], LD4(g_out1 + (n * 3 + m) * 64 + d4));
    __syncwarp();

    // ---- h2 ----
    float4 hv0 = {0,0,0,0}, hv1 = hv0, hv2 = hv0, hv3 = hv0;
#pragma unroll 4
    for (int c = 0; c < Cc; c++) {
        float4 w0 = LD4(Wmix2 + c * 64 + d4);
        float4 w1 = LD4(Wmix2 + 4096 + c * 64 + d4);
        fma4(hv0, w0, As[j][0][c]);
        fma4(hv1, w1, As[j][1][c]);
        fma4(hv2, w1, As[j][2][c]);
        fma4(hv3, w1, As[j][3][c]);
    }

    int el = g_elem[n];
    float4 wv0 = LD4(Wprod2 + el * 64 + d4);
    float4 wv1 = LD4(Wprod2 + NELn * 64 + el * 64 + d4);
    float4 wv2 = LD4(Wprod2 + 2 * NELn * 64 + el * 64 + d4);
    float4 gv;
    gv.x = wv0.x + hv0.x * (wv1.x + hv0.x * wv2.x);
    gv.y = wv0.y + hv0.y * (wv1.y + hv0.y * wv2.y);
    gv.z = wv0.z + hv0.z * (wv1.z + hv0.z * wv2.z);
    gv.w = wv0.w + hv0.w * (wv1.w + hv0.w * wv2.w);

    ST4(&tms[j][0][d4], make_float4(hv1.x*gv.x, hv1.y*gv.y, hv1.z*gv.z, hv1.w*gv.w));
    ST4(&tms[j][1][d4], make_float4(hv2.x*gv.x, hv2.y*gv.y, hv2.z*gv.z, hv2.w*gv.w));
    ST4(&tms[j][2][d4], make_float4(hv3.x*gv.x, hv3.y*gv.y, hv3.z*gv.z, hv3.w*gv.w));
    __syncwarp();

    // ---- out2 = tm @ Wp2 + o1 @ Wsc2[el] ----
    float4 om0 = {0,0,0,0}, om1 = om0, om2 = om0;
    const float* Ws = Wsc2 + el * 4096;
#pragma unroll 4
    for (int c = 0; c < Cc; c++) {
        float4 wsc = LD4(Ws + c * 64 + d4);
        float4 wp  = LD4(Wp2 + c * 64 + d4);
        fma4(om0, wsc, o1s[j][0][c]);
        fma4(om1, wsc, o1s[j][1][c]);
        fma4(om2, wsc, o1s[j][2][c]);
        fma4(om0, wp, tms[j][0][c]);
        fma4(om1, wp, tms[j][1][c]);
        fma4(om2, wp, tms[j][2][c]);
    }
    ST4(&o2s[j][0][d4], om0);
    ST4(&o2s[j][1][d4], om1);
    ST4(&o2s[j][2][d4], om2);
    __syncwarp();

    // ---- vh[m][q] = out2[m] @ Wv[:, q]  (q <-> h, Hh = 16) ----
    float v0 = 0.0f, v1 = 0.0f, v2 = 0.0f;
#pragma unroll 4
    for (int c = 0; c < Cc; c++) {
        float w = Wv[c * Hh + q];
        v0 = fmaf(o2s[j][0][c], w, v0);
        v1 = fmaf(o2s[j][1][c], w, v1);
        v2 = fmaf(o2s[j][2][c], w, v2);
    }
    vhs[j][0][q] = v0;
    vhs[j][1][q] = v1;
    vhs[j][2][q] = v2;
    invs[j][q] = sqrtf(v0 * v0 + v1 * v1 + v2 * v2 + 1e-12f);
    __syncwarp();

    // ---- gate MLP layer 1 (silu) ----
    float pre = bg1[q];
#pragma unroll
    for (int hh = 0; hh < Hh; hh++)
        pre = fmaf(invs[j][hh], Wg1[hh * Hh + q], pre);
    g1s[j][q] = pre / (1.0f + expf(-pre));
    __syncwarp();

    // ---- gate MLP layer 2 * w_read2 ----
    float a = bg2[q];
#pragma unroll
    for (int hh = 0; hh < Hh; hh++)
        a = fmaf(g1s[j][hh], Wg2[hh * Hh + q], a);
    af[j][q] = a * wread2[q];
    __syncwarp();

    // ---- dipole + per-graph totals ----
    if (q < 3) {
        int m = q;
        float d2 = 0.0f;
#pragma unroll
        for (int h = 0; h < Hh; h++)
            d2 = fmaf(vhs[j][m][h], af[j][h], d2);
        float dip = g_d1[n * 3 + m] + d2;
        out[Gg * 3 + n * 3 + m] = dip;
        int g = batch[n];
        atomicAdd(&out[g * 3 + m], dip + charges[n] * pos[n * 3 + m]);
    }
}

// ---------------------------------------------------------------------------
// Host launcher
// ---------------------------------------------------------------------------
extern "C" void kernel_launch(void* const* d_in, const int* in_sizes, int n_in,
                              void* d_out, int out_size) {
    int iei = -1;
    for (int i = 0; i < n_in; i++) {
        if (in_sizes[i] == 2 * Ee) { iei = i; break; }
    }
    if (iei < 0) iei = 4;

    const float* na      = (const float*)d_in[0];
    const float* pos     = (const float*)d_in[1];
    const float* shifts  = (const float*)d_in[2];
    const float* charges = (const float*)d_in[3];
    const int*   ei      = (const int*)d_in[iei];
    const int*   batch   = (const int*)d_in[iei + 1];

    int w;
    if (iei == 4) {
        w = (n_in > 6 && in_sizes[6] == 1) ? 7 : 6;
    } else {
        w = 4;
    }

    const float* W_embed = (const float*)d_in[w + 0];
    const float* Wr1a    = (const float*)d_in[w + 1];
    const float* Wr1b    = (const float*)d_in[w + 2];
    const float* Wmix1   = (const float*)d_in[w + 3];
    const float* Wsc1    = (const float*)d_in[w + 4];
    const float* Wp1s    = (const float*)d_in[w + 5];
    const float* Wp1v    = (const float*)d_in[w + 6];
    const float* Wp10    = (const float*)d_in[w + 7];
    const float* Wp11    = (const float*)d_in[w + 8];
    const float* wread1  = (const float*)d_in[w + 9];
    const float* Wr2a    = (const float*)d_in[w + 10];
    const float* Wr2b    = (const float*)d_in[w + 11];
    const float* Wmix2   = (const float*)d_in[w + 12];
    const float* Wsc2    = (const float*)d_in[w + 13];
    const float* Wprod2  = (const float*)d_in[w + 14];
    const float* Wp2     = (const float*)d_in[w + 15];
    const float* Wv      = (const float*)d_in[w + 16];
    const float* Wg1     = (const float*)d_in[w + 17];
    const float* bg1     = (const float*)d_in[w + 18];
    const float* Wg2     = (const float*)d_in[w + 19];
    const float* bg2     = (const float*)d_in[w + 20];
    const float* wread2  = (const float*)d_in[w + 21];

    float* out = (float*)d_out;

    k_h0<<<Nn, Cc>>>(na, W_embed, out);
    dim3 tg(TBINS + 1, 2);
    k_table<<<tg, 128>>>(Wr1a, Wr1b, Wr2a, Wr2b);
    k_scatter<<<Ee / 256, 256>>>(pos, shifts, ei);
    k_node1<<<Nn / 4, 64>>>(Wmix1, Wsc1, Wp1s, Wp1v, Wp10, Wp11, wread1);
    k_node2<<<Nn / 4, 64>>>(Wmix2, Wsc2, Wprod2, Wp2, Wv, Wg1, bg1, Wg2, bg2,
                            wread2, batch, charges, pos, out);
}